// round 2
// baseline (speedup 1.0000x reference)
#include <cuda_runtime.h>
#include <cuda_bf16.h>

// TreeLSTM over complete binary tree. B=64, L=10, H=E=256, V=64, TOTAL=2046.
// Key optimizations:
//  - xg(x@W+bW) tabulated per vocab id (V=64): Gtab[64][4][256]
//  - leaf h,c tabulated: Htab/Ctab[64][256]
//  - level-9 U-GEMM tabulated per child id: TL/TR[64][5][256]  (halves GEMM work)
//  - levels 8..1: fused GEMM (rows x 512) @ Ucat(5,512,256) + LSTM gating epilogue
//  - [hl|hr] is h_prev reinterpreted as (rows,512) row-major (children adjacent)

#define TOTAL_NODES 2046
#define HD 256

// ---------------- scratch (static device allocations; no cudaMalloc) ----------
__device__ float g_hbuf0[32768 * 256];   // level-9 output (max rows)
__device__ float g_cbuf0[32768 * 256];
__device__ float g_hbuf1[16384 * 256];   // ping-pong partner (max rows at lev 8)
__device__ float g_cbuf1[16384 * 256];
__device__ float g_Gtab[64 * 4 * 256];
__device__ float g_Htab[64 * 256];
__device__ float g_Ctab[64 * 256];
__device__ float g_TL[64 * 5 * 256];
__device__ float g_TR[64 * 5 * 256];
__device__ float g_Ucat[5 * 512 * 256]; // [g][kk][j], kk<256 -> U[g][0][kk][:], else U[g][1][kk-256][:]

__device__ __forceinline__ float sigmf(float x) { return 1.0f / (1.0f + expf(-x)); }

__device__ __forceinline__ unsigned long long fma2(unsigned long long a,
                                                   unsigned long long b,
                                                   unsigned long long c) {
    unsigned long long d;
    asm("fma.rn.f32x2 %0, %1, %2, %3;" : "=l"(d) : "l"(a), "l"(b), "l"(c));
    return d;
}
__device__ __forceinline__ unsigned long long pack2(float x, float y) {
    unsigned long long d;
    asm("mov.b64 %0, {%1, %2};" : "=l"(d) : "f"(x), "f"(y));
    return d;
}
__device__ __forceinline__ void unpack2(unsigned long long d, float& x, float& y) {
    asm("mov.b64 {%0, %1}, %2;" : "=f"(x), "=f"(y) : "l"(d));
}

// ---------------- prep 1: Gtab, Htab, Ctab --------------------------------
// grid 64 (vocab id), block 256 (h)
__global__ void prep1_kernel(const float* __restrict__ emb,
                             const float* __restrict__ W,
                             const float* __restrict__ bW) {
    int v = blockIdx.x;
    int h = threadIdx.x;
    __shared__ float e[256];
    e[h] = emb[v * 256 + h];
    __syncthreads();
    float xg[4];
#pragma unroll
    for (int g = 0; g < 4; g++) {
        float s = bW[g * 256 + h];
        const float* Wg = W + g * 256 * 256 + h;
        for (int k = 0; k < 256; k++) s += e[k] * Wg[k * 256];
        xg[g] = s;
        g_Gtab[v * 1024 + g * 256 + h] = s;
    }
    // leaf: i = sig(xg1), o = sig(xg2), u = tanh(xg3); c = i*u; h = o*tanh(c)
    float ig = sigmf(xg[1]);
    float og = sigmf(xg[2]);
    float ug = tanhf(xg[3]);
    float cc = ig * ug;
    g_Ctab[v * 256 + h] = cc;
    g_Htab[v * 256 + h] = og * tanhf(cc);
}

// ---------------- prep 2: TL/TR ------------------------------------------
// grid (64, 2), block 256 (k)
__global__ void prep2_kernel(const float* __restrict__ U) {
    int v = blockIdx.x;
    int s = blockIdx.y;
    int k = threadIdx.x;
    __shared__ float hh[256];
    hh[k] = g_Htab[v * 256 + k];
    __syncthreads();
    float* T = (s == 0) ? g_TL : g_TR;
#pragma unroll
    for (int g = 0; g < 5; g++) {
        float acc = 0.0f;
        const float* Ug = U + ((g * 2 + s) * 256) * 256 + k;
        for (int h = 0; h < 256; h++) acc += hh[h] * Ug[h * 256];
        T[v * 1280 + g * 256 + k] = acc;
    }
}

// ---------------- prep 3: Ucat repack -------------------------------------
__global__ void prep3_kernel(const float* __restrict__ U) {
    int idx = blockIdx.x * blockDim.x + threadIdx.x;  // 5*512*256 = 655360
    if (idx >= 5 * 512 * 256) return;
    int j = idx & 255;
    int kk = (idx >> 8) & 511;
    int g = idx >> 17;
    int s = kk >> 8;
    int h = kk & 255;
    g_Ucat[idx] = U[((g * 2 + s) * 256 + h) * 256 + j];
}

// ---------------- level 9: pure gather + gating ----------------------------
// grid 32768 (row), block 256 (j)
__global__ void level9_kernel(const int* __restrict__ node_ids,
                              float* __restrict__ hout,
                              float* __restrict__ cout) {
    int row = blockIdx.x;           // b*512 + jn
    int j = threadIdx.x;
    int bb = row >> 9;
    int jn = row & 511;
    const int* nr = node_ids + bb * TOTAL_NODES;
    int id  = nr[510 + jn];
    int idL = nr[1022 + 2 * jn];
    int idR = nr[1023 + 2 * jn];
    const float* tl = g_TL + idL * 1280;
    const float* tr = g_TR + idR * 1280;
    const float* gt = g_Gtab + id * 1024;
    float p0 = tl[j]        + tr[j]        + gt[j];
    float p1 = tl[256 + j]  + tr[256 + j]  + gt[j];
    float p2 = tl[512 + j]  + tr[512 + j]  + gt[256 + j];
    float p3 = tl[768 + j]  + tr[768 + j]  + gt[512 + j];
    float p4 = tl[1024 + j] + tr[1024 + j] + gt[768 + j];
    float cl = g_Ctab[idL * 256 + j];
    float cr = g_Ctab[idR * 256 + j];
    float cc = sigmf(p2) * tanhf(p4) + sigmf(p0) * cl + sigmf(p1) * cr;
    cout[row * 256 + j] = cc;
    hout[row * 256 + j] = sigmf(p3) * tanhf(cc);
}

// ---------------- fused level GEMM + gating (levels 8..1) ------------------
// C(rows,5,256) = A(rows,512) @ Ucat(5,512,256)  then gating epilogue.
// Tile: BM=64 rows, BH=32 hcols, all 5 gates. 256 threads = 16x16.
// Each thread: 4 rows x 2 cols x 5 gates, packed f32x2 accumulators.
#define BM 64
#define BH 32
#define KT 16
__global__ void __launch_bounds__(256)
level_gemm_kernel(const float* __restrict__ hprev,  // (rows,512) view
                  const float* __restrict__ cprev,  // (rows,512) view
                  const int* __restrict__ node_ids,
                  float* __restrict__ hout,
                  float* __restrict__ cout,
                  int lev) {
    const int n = 1 << lev;
    const int off = n - 2;
    const int rbase = blockIdx.x * BM;
    const int hbase = blockIdx.y * BH;

    __shared__ float As[KT][68];         // [k][row], padded stride 68 (16B-aligned rows of 4)
    __shared__ float Us[5][KT][BH];

    const int tid = threadIdx.x;
    const int tx = tid & 15;             // col group: 2 cols
    const int ty = tid >> 4;             // row group: 4 rows

    unsigned long long acc[5][4];
#pragma unroll
    for (int g = 0; g < 5; g++)
#pragma unroll
        for (int i = 0; i < 4; i++) acc[g][i] = 0ull;

    const int a_row = rbase + (tid >> 2);
    const int a_q = (tid & 3) * 4;

    for (int k0 = 0; k0 < 512; k0 += KT) {
        // stage global loads into registers
        float4 av = *(const float4*)(hprev + (size_t)a_row * 512 + k0 + a_q);
        float uv[10];
#pragma unroll
        for (int e = 0; e < 10; e++) {
            int idx = tid + e * 256;
            int j = idx & 31;
            int kk = (idx >> 5) & 15;
            int g = idx >> 9;
            uv[e] = g_Ucat[g * (512 * 256) + (k0 + kk) * 256 + hbase + j];
        }
        __syncthreads();  // previous tile's compute done
        As[a_q + 0][tid >> 2] = av.x;
        As[a_q + 1][tid >> 2] = av.y;
        As[a_q + 2][tid >> 2] = av.z;
        As[a_q + 3][tid >> 2] = av.w;
#pragma unroll
        for (int e = 0; e < 10; e++) {
            int idx = tid + e * 256;
            int j = idx & 31;
            int kk = (idx >> 5) & 15;
            int g = idx >> 9;
            Us[g][kk][j] = uv[e];
        }
        __syncthreads();
#pragma unroll
        for (int k = 0; k < KT; k++) {
            float4 a4 = *(const float4*)&As[k][ty * 4];
            unsigned long long aa0 = pack2(a4.x, a4.x);
            unsigned long long aa1 = pack2(a4.y, a4.y);
            unsigned long long aa2 = pack2(a4.z, a4.z);
            unsigned long long aa3 = pack2(a4.w, a4.w);
#pragma unroll
            for (int g = 0; g < 5; g++) {
                float2 u2 = *(const float2*)&Us[g][k][tx * 2];
                unsigned long long uu = pack2(u2.x, u2.y);
                acc[g][0] = fma2(aa0, uu, acc[g][0]);
                acc[g][1] = fma2(aa1, uu, acc[g][1]);
                acc[g][2] = fma2(aa2, uu, acc[g][2]);
                acc[g][3] = fma2(aa3, uu, acc[g][3]);
            }
        }
    }

    // epilogue: LSTM gating
#pragma unroll
    for (int i = 0; i < 4; i++) {
        int row = rbase + ty * 4 + i;
        int bb = row >> lev;
        int jn = row & (n - 1);
        int id = node_ids[bb * TOTAL_NODES + off + jn];
        const float* gt = g_Gtab + id * 1024;
        float p[5][2];
#pragma unroll
        for (int g = 0; g < 5; g++) unpack2(acc[g][i], p[g][0], p[g][1]);
#pragma unroll
        for (int jj = 0; jj < 2; jj++) {
            int j = hbase + tx * 2 + jj;
            float p0 = p[0][jj] + gt[j];
            float p1 = p[1][jj] + gt[j];
            float p2 = p[2][jj] + gt[256 + j];
            float p3 = p[3][jj] + gt[512 + j];
            float p4 = p[4][jj] + gt[768 + j];
            float cl = cprev[(size_t)row * 512 + j];
            float cr = cprev[(size_t)row * 512 + 256 + j];
            float cc = sigmf(p2) * tanhf(p4) + sigmf(p0) * cl + sigmf(p1) * cr;
            cout[(size_t)row * 256 + j] = cc;
            hout[(size_t)row * 256 + j] = sigmf(p3) * tanhf(cc);
        }
    }
}

// ---------------- final: scores + root_hidden ------------------------------
// grid 64 (b), block 256
__global__ void final_kernel(const float* __restrict__ h1,  // (64, 512)
                             const float* __restrict__ Wsm, // (512,3)
                             const float* __restrict__ bs,
                             float* __restrict__ out, int out_size) {
    int b = blockIdx.x;
    int t = threadIdx.x;
    if (out_size >= 192 + 64 * 512) {
        out[192 + b * 512 + t] = h1[b * 512 + t];
        out[192 + b * 512 + 256 + t] = h1[b * 512 + 256 + t];
    }
    if (t < 3) {
        float s = bs[t];
        for (int j = 0; j < 512; j++) s += h1[b * 512 + j] * Wsm[j * 3 + t];
        out[b * 3 + t] = s;
    }
}

extern "C" void kernel_launch(void* const* d_in, const int* in_sizes, int n_in,
                              void* d_out, int out_size) {
    const int* node_ids = (const int*)d_in[0];
    const float* emb = (const float*)d_in[1];
    const float* W = (const float*)d_in[2];
    const float* bW = (const float*)d_in[3];
    const float* U = (const float*)d_in[4];
    const float* Ws = (const float*)d_in[5];
    const float* bs = (const float*)d_in[6];
    float* out = (float*)d_out;

    float *hb0, *cb0, *hb1, *cb1;
    cudaGetSymbolAddress((void**)&hb0, g_hbuf0);
    cudaGetSymbolAddress((void**)&cb0, g_cbuf0);
    cudaGetSymbolAddress((void**)&hb1, g_hbuf1);
    cudaGetSymbolAddress((void**)&cb1, g_cbuf1);

    prep1_kernel<<<64, 256>>>(emb, W, bW);
    prep2_kernel<<<dim3(64, 2), 256>>>(U);
    prep3_kernel<<<640, 1024>>>(U);

    level9_kernel<<<32768, 256>>>(node_ids, hb0, cb0);

    float *hp = hb0, *cp = cb0, *hc = hb1, *cc = cb1;
    for (int lev = 8; lev >= 1; lev--) {
        int rows = 64 << lev;
        dim3 grid(rows / BM, HD / BH);
        level_gemm_kernel<<<grid, 256>>>(hp, cp, node_ids, hc, cc, lev);
        float* t;
        t = hp; hp = hc; hc = t;
        t = cp; cp = cc; cc = t;
    }
    // after 8 swaps, hp holds level-1 h (64 rows x 2 x 256 = (64,512))
    final_kernel<<<64, 256>>>(hp, Ws, bs, out, out_size);
}

// round 6
// speedup vs baseline: 1.4384x; 1.4384x over previous
#include <cuda_runtime.h>
#include <cuda_bf16.h>
#include <cstdint>

// TreeLSTM B=64, L=10, H=E=256, V=64, TOTAL=2046.
//  - Gtab/Htab/Ctab tabulated per vocab id; level-9 U-GEMM tabulated (TL/TR)
//  - levels 8..1: mma.sync bf16 (3-pass hi/lo split, fp32 accumulate) fused
//    with LSTM gating epilogue. h and U stored as separate bf16 hi/lo planes.

#define TOTAL_NODES 2046

// ---------------- scratch ----------------
__device__ __nv_bfloat16 g_hhi0[32768 * 256];
__device__ __nv_bfloat16 g_hlo0[32768 * 256];
__device__ float         g_c0  [32768 * 256];
__device__ __nv_bfloat16 g_hhi1[16384 * 256];
__device__ __nv_bfloat16 g_hlo1[16384 * 256];
__device__ float         g_c1  [16384 * 256];
__device__ float g_Gtab[64 * 4 * 256];
__device__ float g_Htab[64 * 256];
__device__ float g_Ctab[64 * 256];
__device__ float g_TL[64 * 5 * 256];
__device__ float g_TR[64 * 5 * 256];
__device__ __nv_bfloat16 g_Bhi[5 * 256 * 512];   // [g][n][k]  k = s*256+h
__device__ __nv_bfloat16 g_Blo[5 * 256 * 512];

// ---------------- helpers ----------------
__device__ __forceinline__ float ftanh(float x) {
    float y; asm("tanh.approx.f32 %0, %1;" : "=f"(y) : "f"(x)); return y;
}
__device__ __forceinline__ float fsig(float x) { return 0.5f * ftanh(0.5f * x) + 0.5f; }

__device__ __forceinline__ uint32_t smem_u32(const void* p) {
    uint32_t a;
    asm("{ .reg .u64 t; cvta.to.shared.u64 t, %1; cvt.u32.u64 %0, t; }" : "=r"(a) : "l"(p));
    return a;
}

#define CP_ASYNC16(dst, src) \
    asm volatile("cp.async.cg.shared.global [%0], [%1], 16;" :: "r"(dst), "l"(src) : "memory")
#define CP_COMMIT() asm volatile("cp.async.commit_group;" ::: "memory")
#define CP_WAIT1()  asm volatile("cp.async.wait_group 1;" ::: "memory")

#define LDSM4(r, a) \
    asm volatile("ldmatrix.sync.aligned.m8n8.x4.shared.b16 {%0,%1,%2,%3}, [%4];" \
        : "=r"((r)[0]), "=r"((r)[1]), "=r"((r)[2]), "=r"((r)[3]) : "r"(a))

#define MMA16816(c, a, b0, b1) \
    asm volatile("mma.sync.aligned.m16n8k16.row.col.f32.bf16.bf16.f32 " \
        "{%0,%1,%2,%3}, {%4,%5,%6,%7}, {%8,%9}, {%0,%1,%2,%3};" \
        : "+f"((c)[0]), "+f"((c)[1]), "+f"((c)[2]), "+f"((c)[3]) \
        : "r"((a)[0]), "r"((a)[1]), "r"((a)[2]), "r"((a)[3]), "r"(b0), "r"(b1))

// ---------------- prep 1: Gtab, Htab, Ctab --------------------------------
__global__ void prep1_kernel(const float* __restrict__ emb,
                             const float* __restrict__ W,
                             const float* __restrict__ bW) {
    int v = blockIdx.x;
    int h = threadIdx.x;
    __shared__ float e[256];
    e[h] = emb[v * 256 + h];
    __syncthreads();
    float xg[4];
#pragma unroll
    for (int g = 0; g < 4; g++) {
        float s = bW[g * 256 + h];
        const float* Wg = W + g * 256 * 256 + h;
        for (int k = 0; k < 256; k++) s += e[k] * Wg[k * 256];
        xg[g] = s;
        g_Gtab[v * 1024 + g * 256 + h] = s;
    }
    float ig = fsig(xg[1]);
    float og = fsig(xg[2]);
    float ug = ftanh(xg[3]);
    float cc = ig * ug;
    g_Ctab[v * 256 + h] = cc;
    g_Htab[v * 256 + h] = og * ftanh(cc);
}

// ---------------- prep 2: TL/TR ------------------------------------------
__global__ void prep2_kernel(const float* __restrict__ U) {
    int v = blockIdx.x;
    int s = blockIdx.y;
    int k = threadIdx.x;
    __shared__ float hh[256];
    hh[k] = g_Htab[v * 256 + k];
    __syncthreads();
    float* T = (s == 0) ? g_TL : g_TR;
#pragma unroll
    for (int g = 0; g < 5; g++) {
        float acc = 0.0f;
        const float* Ug = U + ((g * 2 + s) * 256) * 256 + k;
        for (int h = 0; h < 256; h++) acc += hh[h] * Ug[h * 256];
        T[v * 1280 + g * 256 + k] = acc;
    }
}

// ---------------- prep 3: B hi/lo planes [g][n][k] -------------------------
__global__ void prep3_kernel(const float* __restrict__ U) {
    int idx = blockIdx.x * blockDim.x + threadIdx.x;  // 5*256*512 = 655360
    if (idx >= 5 * 256 * 512) return;
    int k = idx & 511;
    int n = (idx >> 9) & 255;
    int g = idx >> 17;
    int s = k >> 8;
    int h = k & 255;
    float v = U[((g * 2 + s) * 256 + h) * 256 + n];
    __nv_bfloat16 hi = __float2bfloat16(v);
    g_Bhi[idx] = hi;
    g_Blo[idx] = __float2bfloat16(v - __bfloat162float(hi));
}

// ---------------- level 9: gather + gating --------------------------------
__global__ void level9_kernel(const int* __restrict__ node_ids,
                              __nv_bfloat16* __restrict__ hhi,
                              __nv_bfloat16* __restrict__ hlo,
                              float* __restrict__ cout) {
    int row = blockIdx.x;
    int j = threadIdx.x;
    int bb = row >> 9;
    int jn = row & 511;
    const int* nr = node_ids + bb * TOTAL_NODES;
    int id  = nr[510 + jn];
    int idL = nr[1022 + 2 * jn];
    int idR = nr[1023 + 2 * jn];
    const float* tl = g_TL + idL * 1280;
    const float* tr = g_TR + idR * 1280;
    const float* gt = g_Gtab + id * 1024;
    float p0 = tl[j]        + tr[j]        + gt[j];
    float p1 = tl[256 + j]  + tr[256 + j]  + gt[j];
    float p2 = tl[512 + j]  + tr[512 + j]  + gt[256 + j];
    float p3 = tl[768 + j]  + tr[768 + j]  + gt[512 + j];
    float p4 = tl[1024 + j] + tr[1024 + j] + gt[768 + j];
    float cl = g_Ctab[idL * 256 + j];
    float cr = g_Ctab[idR * 256 + j];
    float cc = fsig(p2) * ftanh(p4) + fsig(p0) * cl + fsig(p1) * cr;
    cout[row * 256 + j] = cc;
    float hh = fsig(p3) * ftanh(cc);
    __nv_bfloat16 hi = __float2bfloat16(hh);
    hhi[row * 256 + j] = hi;
    hlo[row * 256 + j] = __float2bfloat16(hh - __bfloat162float(hi));
}

// ---------------- mma.sync level kernel (levels 8..1) ----------------------
// CTA: 128 rows x (5 gates x 64 j = 320 N), K=512 in 16 chunks of 32.
// 8 warps (2 x 4), warp tile 64 x 80. 3-pass bf16 hi/lo.
// SMEM stage: Ahi[128][40] Alo[128][40] Bhi[320][40] Blo[320][40] bf16 (70KB), x2.
#define STG 71680
#define OFF_AHI 0
#define OFF_ALO 10240
#define OFF_BHI 20480
#define OFF_BLO 46080
#define SMEM_REQ 168960

__global__ void __launch_bounds__(256, 1)
mma_level_kernel(const __nv_bfloat16* __restrict__ Ahi_g,  // (rows,512) view
                 const __nv_bfloat16* __restrict__ Alo_g,
                 const float* __restrict__ c_prev,          // (rows,512) view
                 const int* __restrict__ node_ids,
                 __nv_bfloat16* __restrict__ hhi_out,
                 __nv_bfloat16* __restrict__ hlo_out,
                 float* __restrict__ c_out,
                 int lev) {
    extern __shared__ __align__(128) char dsm[];
    const uint32_t sbase = smem_u32(dsm);

    const int rbase = blockIdx.x * 128;
    const int jbase = blockIdx.y * 64;
    const int tid = threadIdx.x;
    const int wid = tid >> 5;
    const int lid = tid & 31;
    const int wr = wid >> 2;       // warp row (0..1): m0 = wr*64
    const int wc = wid & 3;        // warp col (0..3): n0 = wc*80

    float acc[4][10][4];
#pragma unroll
    for (int i = 0; i < 4; i++)
#pragma unroll
        for (int j = 0; j < 10; j++)
#pragma unroll
            for (int e = 0; e < 4; e++) acc[i][j][e] = 0.0f;

    // per-lane ldmatrix offsets (bytes)
    const uint32_t a_lane = (uint32_t)((lid & 15) * 80 + (lid >> 4) * 16);
    const uint32_t b_lane = (uint32_t)(((lid & 7) + (lid >> 4) * 8) * 80 + ((lid >> 3) & 1) * 16);

    // ---- async copy of one chunk into stage st ----
    auto load_chunk = [&](int kc, int st) {
        const uint32_t S = sbase + st * STG;
        const int k0 = kc * 32;
        // A: 2 planes x 128 rows x 4 segs (8 bf16 each) = 1024 copies, 4/thread
#pragma unroll
        for (int i = 0; i < 4; i++) {
            int c = i * 256 + tid;
            int plane = c >> 9;                 // 512 per plane
            int rem = c & 511;
            int r = rem >> 2;
            int sg = rem & 3;
            const __nv_bfloat16* src = (plane ? Alo_g : Ahi_g) +
                (size_t)(rbase + r) * 512 + k0 + sg * 8;
            uint32_t dst = S + (plane ? OFF_ALO : OFF_AHI) + r * 80 + sg * 16;
            CP_ASYNC16(dst, src);
        }
        // B: 2 planes x 320 n x 4 segs = 2560 copies (1280 per plane), 10/thread
#pragma unroll
        for (int i = 0; i < 10; i++) {
            int c = i * 256 + tid;
            int plane = (c >= 1280) ? 1 : 0;    // 1280 per plane (FIXED)
            int rem = c - plane * 1280;
            int n = rem >> 2;
            int sg = rem & 3;
            int g = n >> 6;
            int jj = n & 63;
            const __nv_bfloat16* src = (plane ? g_Blo : g_Bhi) +
                (size_t)(g * 256 + jbase + jj) * 512 + k0 + sg * 8;
            uint32_t dst = S + (plane ? OFF_BLO : OFF_BHI) + n * 80 + sg * 16;
            CP_ASYNC16(dst, src);
        }
    };

    load_chunk(0, 0);
    CP_COMMIT();

    for (int kc = 0; kc < 16; kc++) {
        if (kc + 1 < 16) load_chunk(kc + 1, (kc + 1) & 1);
        CP_COMMIT();
        CP_WAIT1();
        __syncthreads();

        const uint32_t S = sbase + (kc & 1) * STG;
        const uint32_t sAh = S + OFF_AHI + wr * 5120 + a_lane;
        const uint32_t sAl = S + OFF_ALO + wr * 5120 + a_lane;
        const uint32_t sBh = S + OFF_BHI + wc * 6400 + b_lane;
        const uint32_t sBl = S + OFF_BLO + wc * 6400 + b_lane;

#pragma unroll
        for (int kk = 0; kk < 2; kk++) {
            const uint32_t ko = kk * 32;
            uint32_t ah[4][4], al[4][4], bm[5][4];
#pragma unroll
            for (int i = 0; i < 4; i++) LDSM4(ah[i], sAh + i * 1280 + ko);
#pragma unroll
            for (int i = 0; i < 4; i++) LDSM4(al[i], sAl + i * 1280 + ko);
#pragma unroll
            for (int jp = 0; jp < 5; jp++) LDSM4(bm[jp], sBh + jp * 1280 + ko);
            // hi*hi and lo*hi
#pragma unroll
            for (int i = 0; i < 4; i++)
#pragma unroll
                for (int jp = 0; jp < 5; jp++) {
                    MMA16816(acc[i][2 * jp],     ah[i], bm[jp][0], bm[jp][1]);
                    MMA16816(acc[i][2 * jp + 1], ah[i], bm[jp][2], bm[jp][3]);
                    MMA16816(acc[i][2 * jp],     al[i], bm[jp][0], bm[jp][1]);
                    MMA16816(acc[i][2 * jp + 1], al[i], bm[jp][2], bm[jp][3]);
                }
            // hi*lo
#pragma unroll
            for (int jp = 0; jp < 5; jp++) LDSM4(bm[jp], sBl + jp * 1280 + ko);
#pragma unroll
            for (int i = 0; i < 4; i++)
#pragma unroll
                for (int jp = 0; jp < 5; jp++) {
                    MMA16816(acc[i][2 * jp],     ah[i], bm[jp][0], bm[jp][1]);
                    MMA16816(acc[i][2 * jp + 1], ah[i], bm[jp][2], bm[jp][3]);
                }
        }
        __syncthreads();
    }

    // ---- epilogue: C -> smem, gate, store ----
    float* Csm = (float*)dsm;            // [128][328]
    __shared__ int s_id[128];
    const int n = 1 << lev;
    const int off = n - 2;
    if (tid < 128) {
        int row = rbase + tid;
        int bb = row >> lev;
        int jn = row & (n - 1);
        s_id[tid] = node_ids[bb * TOTAL_NODES + off + jn];
    }
    {
        const int m0 = wr * 64;
        const int n0 = wc * 80;
        const int mr = lid >> 2;
        const int nc = (lid & 3) * 2;
#pragma unroll
        for (int i = 0; i < 4; i++)
#pragma unroll
            for (int j = 0; j < 10; j++) {
                int m = m0 + i * 16 + mr;
                int nn = n0 + j * 8 + nc;
                *(float2*)&Csm[m * 328 + nn] = make_float2(acc[i][j][0], acc[i][j][1]);
                *(float2*)&Csm[(m + 8) * 328 + nn] = make_float2(acc[i][j][2], acc[i][j][3]);
            }
    }
    __syncthreads();

    const int j = tid & 63;
    const int jg = jbase + j;
#pragma unroll 4
    for (int m = (tid >> 6); m < 128; m += 4) {
        const float* gt = g_Gtab + s_id[m] * 1024;
        const float* Cr = Csm + m * 328 + j;
        int row = rbase + m;
        float p0 = Cr[0]   + gt[jg];
        float p1 = Cr[64]  + gt[jg];
        float p2 = Cr[128] + gt[256 + jg];
        float p3 = Cr[192] + gt[512 + jg];
        float p4 = Cr[256] + gt[768 + jg];
        float cl = c_prev[(size_t)row * 512 + jg];
        float cr = c_prev[(size_t)row * 512 + 256 + jg];
        float cc = fsig(p2) * ftanh(p4) + fsig(p0) * cl + fsig(p1) * cr;
        float hh = fsig(p3) * ftanh(cc);
        size_t o = (size_t)row * 256 + jg;
        c_out[o] = cc;
        __nv_bfloat16 hi = __float2bfloat16(hh);
        hhi_out[o] = hi;
        hlo_out[o] = __float2bfloat16(hh - __bfloat162float(hi));
    }
}

// ---------------- final: scores + root_hidden ------------------------------
__global__ void final_kernel(const __nv_bfloat16* __restrict__ hhi,  // (128,256)
                             const __nv_bfloat16* __restrict__ hlo,
                             const float* __restrict__ Wsm,
                             const float* __restrict__ bs,
                             float* __restrict__ out, int out_size) {
    int b = blockIdx.x;
    int t = threadIdx.x;
    __shared__ float hs[512];
    for (int jj = t; jj < 512; jj += 256) {
        float v = __bfloat162float(hhi[b * 512 + jj]) + __bfloat162float(hlo[b * 512 + jj]);
        hs[jj] = v;
        if (out_size >= 192 + 64 * 512) out[192 + b * 512 + jj] = v;
    }
    __syncthreads();
    if (t < 3) {
        float s = bs[t];
        for (int jj = 0; jj < 512; jj++) s += hs[jj] * Wsm[jj * 3 + t];
        out[b * 3 + t] = s;
    }
}

extern "C" void kernel_launch(void* const* d_in, const int* in_sizes, int n_in,
                              void* d_out, int out_size) {
    const int* node_ids = (const int*)d_in[0];
    const float* emb = (const float*)d_in[1];
    const float* W = (const float*)d_in[2];
    const float* bW = (const float*)d_in[3];
    const float* U = (const float*)d_in[4];
    const float* Ws = (const float*)d_in[5];
    const float* bs = (const float*)d_in[6];
    float* out = (float*)d_out;

    __nv_bfloat16 *hhi0, *hlo0, *hhi1, *hlo1;
    float *c0, *c1;
    cudaGetSymbolAddress((void**)&hhi0, g_hhi0);
    cudaGetSymbolAddress((void**)&hlo0, g_hlo0);
    cudaGetSymbolAddress((void**)&c0, g_c0);
    cudaGetSymbolAddress((void**)&hhi1, g_hhi1);
    cudaGetSymbolAddress((void**)&hlo1, g_hlo1);
    cudaGetSymbolAddress((void**)&c1, g_c1);

    cudaFuncSetAttribute(mma_level_kernel,
                         cudaFuncAttributeMaxDynamicSharedMemorySize, SMEM_REQ);

    prep1_kernel<<<64, 256>>>(emb, W, bW);
    prep2_kernel<<<dim3(64, 2), 256>>>(U);
    prep3_kernel<<<640, 1024>>>(U);

    level9_kernel<<<32768, 256>>>(node_ids, hhi0, hlo0, c0);

    __nv_bfloat16 *hip = hhi0, *lop = hlo0, *hic = hhi1, *loc = hlo1;
    float *cp = c0, *cc = c1;
    for (int lev = 8; lev >= 1; lev--) {
        int rows = 64 << lev;
        dim3 grid(rows / 128, 4);
        mma_level_kernel<<<grid, 256, SMEM_REQ>>>(hip, lop, cp, node_ids,
                                                  hic, loc, cc, lev);
        __nv_bfloat16* t;
        t = hip; hip = hic; hic = t;
        t = lop; lop = loc; loc = t;
        float* t2 = cp; cp = cc; cc = t2;
    }
    final_kernel<<<64, 256>>>(hip, lop, Ws, bs, out, out_size);
}

// round 7
// speedup vs baseline: 2.0107x; 1.3979x over previous
#include <cuda_runtime.h>
#include <cuda_fp16.h>
#include <cstdint>

// TreeLSTM B=64, L=10, H=E=256, V=64, TOTAL=2046.
//  - Gtab/Htab/Ctab tabulated per vocab id; level-9 U-GEMM tabulated (TL/TR)
//  - levels 8..1: mma.sync fp16 (2-pass: A split hi/lo fp16, B rounded fp16)
//    fused with LSTM gating epilogue. Template tile-M (128 big / 32 small levels).

#define TOTAL_NODES 2046

// ---------------- scratch ----------------
__device__ __half g_hhi0[32768 * 256];
__device__ __half g_hlo0[32768 * 256];
__device__ float  g_c0  [32768 * 256];
__device__ __half g_hhi1[16384 * 256];
__device__ __half g_hlo1[16384 * 256];
__device__ float  g_c1  [16384 * 256];
__device__ float g_Gtab[64 * 4 * 256];
__device__ float g_Htab[64 * 256];
__device__ float g_Ctab[64 * 256];
__device__ float g_TL[64 * 5 * 256];
__device__ float g_TR[64 * 5 * 256];
__device__ __half g_Bh[5 * 256 * 512];   // [g][n][k]  k = s*256+h, fp16 rounded

// ---------------- helpers ----------------
__device__ __forceinline__ float ftanh(float x) {
    float y; asm("tanh.approx.f32 %0, %1;" : "=f"(y) : "f"(x)); return y;
}
__device__ __forceinline__ float fsig(float x) { return 0.5f * ftanh(0.5f * x) + 0.5f; }

__device__ __forceinline__ uint32_t smem_u32(const void* p) {
    uint32_t a;
    asm("{ .reg .u64 t; cvta.to.shared.u64 t, %1; cvt.u32.u64 %0, t; }" : "=r"(a) : "l"(p));
    return a;
}

#define CP_ASYNC16(dst, src) \
    asm volatile("cp.async.cg.shared.global [%0], [%1], 16;" :: "r"(dst), "l"(src) : "memory")
#define CP_COMMIT() asm volatile("cp.async.commit_group;" ::: "memory")
#define CP_WAIT2()  asm volatile("cp.async.wait_group 2;" ::: "memory")

#define LDSM4(r, a) \
    asm volatile("ldmatrix.sync.aligned.m8n8.x4.shared.b16 {%0,%1,%2,%3}, [%4];" \
        : "=r"((r)[0]), "=r"((r)[1]), "=r"((r)[2]), "=r"((r)[3]) : "r"(a))

#define MMA16816(c, a, b0, b1) \
    asm volatile("mma.sync.aligned.m16n8k16.row.col.f32.f16.f16.f32 " \
        "{%0,%1,%2,%3}, {%4,%5,%6,%7}, {%8,%9}, {%0,%1,%2,%3};" \
        : "+f"((c)[0]), "+f"((c)[1]), "+f"((c)[2]), "+f"((c)[3]) \
        : "r"((a)[0]), "r"((a)[1]), "r"((a)[2]), "r"((a)[3]), "r"(b0), "r"(b1))

__device__ __forceinline__ void split_h(float v, __half& hi, __half& lo) {
    hi = __float2half_rn(v);
    lo = __float2half_rn(v - __half2float(hi));
}

// ---------------- prep 1: Gtab, Htab, Ctab --------------------------------
__global__ void prep1_kernel(const float* __restrict__ emb,
                             const float* __restrict__ W,
                             const float* __restrict__ bW) {
    int v = blockIdx.x;
    int h = threadIdx.x;
    __shared__ float e[256];
    e[h] = emb[v * 256 + h];
    __syncthreads();
    float xg[4];
#pragma unroll
    for (int g = 0; g < 4; g++) {
        float s = bW[g * 256 + h];
        const float* Wg = W + g * 256 * 256 + h;
        for (int k = 0; k < 256; k++) s += e[k] * Wg[k * 256];
        xg[g] = s;
        g_Gtab[v * 1024 + g * 256 + h] = s;
    }
    float ig = fsig(xg[1]);
    float og = fsig(xg[2]);
    float ug = ftanh(xg[3]);
    float cc = ig * ug;
    g_Ctab[v * 256 + h] = cc;
    g_Htab[v * 256 + h] = og * ftanh(cc);
}

// ---------------- prep 2: TL/TR ------------------------------------------
__global__ void prep2_kernel(const float* __restrict__ U) {
    int v = blockIdx.x;
    int s = blockIdx.y;
    int k = threadIdx.x;
    __shared__ float hh[256];
    hh[k] = g_Htab[v * 256 + k];
    __syncthreads();
    float* T = (s == 0) ? g_TL : g_TR;
#pragma unroll
    for (int g = 0; g < 5; g++) {
        float acc = 0.0f;
        const float* Ug = U + ((g * 2 + s) * 256) * 256 + k;
        for (int h = 0; h < 256; h++) acc += hh[h] * Ug[h * 256];
        T[v * 1280 + g * 256 + k] = acc;
    }
}

// ---------------- prep 3: B fp16 plane [g][n][k] ---------------------------
__global__ void prep3_kernel(const float* __restrict__ U) {
    int idx = blockIdx.x * blockDim.x + threadIdx.x;  // 5*256*512 = 655360
    if (idx >= 5 * 256 * 512) return;
    int k = idx & 511;
    int n = (idx >> 9) & 255;
    int g = idx >> 17;
    int s = k >> 8;
    int h = k & 255;
    g_Bh[idx] = __float2half_rn(U[((g * 2 + s) * 256 + h) * 256 + n]);
}

// ---------------- level 9: gather + gating --------------------------------
__global__ void level9_kernel(const int* __restrict__ node_ids,
                              __half* __restrict__ hhi,
                              __half* __restrict__ hlo,
                              float* __restrict__ cout) {
    int row = blockIdx.x;
    int j = threadIdx.x;
    int bb = row >> 9;
    int jn = row & 511;
    const int* nr = node_ids + bb * TOTAL_NODES;
    int id  = nr[510 + jn];
    int idL = nr[1022 + 2 * jn];
    int idR = nr[1023 + 2 * jn];
    const float* tl = g_TL + idL * 1280;
    const float* tr = g_TR + idR * 1280;
    const float* gt = g_Gtab + id * 1024;
    float p0 = tl[j]        + tr[j]        + gt[j];
    float p1 = tl[256 + j]  + tr[256 + j]  + gt[j];
    float p2 = tl[512 + j]  + tr[512 + j]  + gt[256 + j];
    float p3 = tl[768 + j]  + tr[768 + j]  + gt[512 + j];
    float p4 = tl[1024 + j] + tr[1024 + j] + gt[768 + j];
    float cl = g_Ctab[idL * 256 + j];
    float cr = g_Ctab[idR * 256 + j];
    float cc = fsig(p2) * ftanh(p4) + fsig(p0) * cl + fsig(p1) * cr;
    cout[row * 256 + j] = cc;
    float hh = fsig(p3) * ftanh(cc);
    __half hi, lo;
    split_h(hh, hi, lo);
    hhi[row * 256 + j] = hi;
    hlo[row * 256 + j] = lo;
}

// ---------------- mma.sync level kernel (levels 8..1) ----------------------
// CTA: CM rows x (5 gates x 64 j = 320 N), K=512 in 16 chunks of 32.
// 8 warps (2 x 4), warp tile (CM/2) x 80. 2-pass fp16 (A hi + A lo) x B.
// SMEM stage: Ahi[CM][40] Alo[CM][40] B[320][40] fp16, rows padded to 80B.
#define SMEM_REQ 168960

template <int CM>
__global__ void __launch_bounds__(256, 1)
mma_level_kernel(const __half* __restrict__ Ahi_g,  // (rows,512) view
                 const __half* __restrict__ Alo_g,
                 const float* __restrict__ c_prev,   // (rows,512) view
                 const int* __restrict__ node_ids,
                 __half* __restrict__ hhi_out,
                 __half* __restrict__ hlo_out,
                 float* __restrict__ c_out,
                 int lev) {
    constexpr int WM = CM / 2;          // warp tile M
    constexpr int NI = WM / 16;         // m16 fragments per warp
    constexpr int OFF_ALO = CM * 80;
    constexpr int OFF_B   = 2 * CM * 80;
    constexpr int STG     = 2 * CM * 80 + 320 * 80;
    constexpr int ACPT    = (CM * 8) / 256;   // A cp.async per thread

    extern __shared__ __align__(128) char dsm[];
    const uint32_t sbase = smem_u32(dsm);

    const int rbase = blockIdx.x * CM;
    const int jbase = blockIdx.y * 64;
    const int tid = threadIdx.x;
    const int wid = tid >> 5;
    const int lid = tid & 31;
    const int wr = wid >> 2;       // warp row (0..1): m0 = wr*WM
    const int wc = wid & 3;        // warp col (0..3): n0 = wc*80

    float acc[NI][10][4];
#pragma unroll
    for (int i = 0; i < NI; i++)
#pragma unroll
        for (int j = 0; j < 10; j++)
#pragma unroll
            for (int e = 0; e < 4; e++) acc[i][j][e] = 0.0f;

    const uint32_t a_lane = (uint32_t)((lid & 15) * 80 + (lid >> 4) * 16);
    const uint32_t b_lane = (uint32_t)(((lid & 7) + (lid >> 4) * 8) * 80 + ((lid >> 3) & 1) * 16);

    auto load_chunk = [&](int kc, int st) {
        const uint32_t S = sbase + st * STG;
        const int k0 = kc * 32;
        // A: 2 planes x CM rows x 4 segs(16B)
#pragma unroll
        for (int i = 0; i < ACPT; i++) {
            int c = i * 256 + tid;
            int plane = c / (4 * CM);
            int rem = c - plane * 4 * CM;
            int r = rem >> 2;
            int sg = rem & 3;
            const __half* src = (plane ? Alo_g : Ahi_g) +
                (size_t)(rbase + r) * 512 + k0 + sg * 8;
            uint32_t dst = S + (plane ? OFF_ALO : 0) + r * 80 + sg * 16;
            CP_ASYNC16(dst, src);
        }
        // B: 320 n x 4 segs = 1280 copies, 5/thread
#pragma unroll
        for (int i = 0; i < 5; i++) {
            int c = i * 256 + tid;
            int n = c >> 2;
            int sg = c & 3;
            int g = n >> 6;
            int jj = n & 63;
            const __half* src = g_Bh + (size_t)(g * 256 + jbase + jj) * 512 + k0 + sg * 8;
            uint32_t dst = S + OFF_B + n * 80 + sg * 16;
            CP_ASYNC16(dst, src);
        }
    };

    load_chunk(0, 0); CP_COMMIT();
    load_chunk(1, 1); CP_COMMIT();

    for (int kc = 0; kc < 16; kc++) {
        if (kc + 2 < 16) load_chunk(kc + 2, (kc + 2) % 3);
        CP_COMMIT();
        CP_WAIT2();
        __syncthreads();

        const uint32_t S = sbase + (kc % 3) * STG;
        const uint32_t sAh = S + wr * (WM * 80) + a_lane;
        const uint32_t sAl = S + OFF_ALO + wr * (WM * 80) + a_lane;
        const uint32_t sB  = S + OFF_B + wc * 6400 + b_lane;

#pragma unroll
        for (int kk = 0; kk < 2; kk++) {
            const uint32_t ko = kk * 32;
            uint32_t ah[NI][4], al[NI][4], bm[5][4];
#pragma unroll
            for (int i = 0; i < NI; i++) LDSM4(ah[i], sAh + i * 1280 + ko);
#pragma unroll
            for (int i = 0; i < NI; i++) LDSM4(al[i], sAl + i * 1280 + ko);
#pragma unroll
            for (int jp = 0; jp < 5; jp++) LDSM4(bm[jp], sB + jp * 1280 + ko);
            // pass 1: A_hi * B   (no RAW between consecutive MMAs)
#pragma unroll
            for (int i = 0; i < NI; i++)
#pragma unroll
                for (int jp = 0; jp < 5; jp++) {
                    MMA16816(acc[i][2 * jp],     ah[i], bm[jp][0], bm[jp][1]);
                    MMA16816(acc[i][2 * jp + 1], ah[i], bm[jp][2], bm[jp][3]);
                }
            // pass 2: A_lo * B
#pragma unroll
            for (int i = 0; i < NI; i++)
#pragma unroll
                for (int jp = 0; jp < 5; jp++) {
                    MMA16816(acc[i][2 * jp],     al[i], bm[jp][0], bm[jp][1]);
                    MMA16816(acc[i][2 * jp + 1], al[i], bm[jp][2], bm[jp][3]);
                }
        }
        __syncthreads();
    }

    // ---- epilogue: C -> smem, gate, store ----
    float* Csm = (float*)dsm;            // [CM][328]
    __shared__ int s_id[CM];
    const int n = 1 << lev;
    const int off = n - 2;
    if (tid < CM) {
        int row = rbase + tid;
        int bb = row >> lev;
        int jn = row & (n - 1);
        s_id[tid] = node_ids[bb * TOTAL_NODES + off + jn];
    }
    {
        const int m0 = wr * WM;
        const int n0 = wc * 80;
        const int mr = lid >> 2;
        const int nc = (lid & 3) * 2;
#pragma unroll
        for (int i = 0; i < NI; i++)
#pragma unroll
            for (int j = 0; j < 10; j++) {
                int m = m0 + i * 16 + mr;
                int nn = n0 + j * 8 + nc;
                *(float2*)&Csm[m * 328 + nn] = make_float2(acc[i][j][0], acc[i][j][1]);
                *(float2*)&Csm[(m + 8) * 328 + nn] = make_float2(acc[i][j][2], acc[i][j][3]);
            }
    }
    __syncthreads();

    const int j = tid & 63;
    const int jg = jbase + j;
#pragma unroll 4
    for (int m = (tid >> 6); m < CM; m += 4) {
        const float* gt = g_Gtab + s_id[m] * 1024;
        const float* Cr = Csm + m * 328 + j;
        int row = rbase + m;
        float p0 = Cr[0]   + gt[jg];
        float p1 = Cr[64]  + gt[jg];
        float p2 = Cr[128] + gt[256 + jg];
        float p3 = Cr[192] + gt[512 + jg];
        float p4 = Cr[256] + gt[768 + jg];
        float cl = c_prev[(size_t)row * 512 + jg];
        float cr = c_prev[(size_t)row * 512 + 256 + jg];
        float cc = fsig(p2) * ftanh(p4) + fsig(p0) * cl + fsig(p1) * cr;
        float hh = fsig(p3) * ftanh(cc);
        size_t o = (size_t)row * 256 + jg;
        c_out[o] = cc;
        __half hi, lo;
        split_h(hh, hi, lo);
        hhi_out[o] = hi;
        hlo_out[o] = lo;
    }
}

// ---------------- final: scores + root_hidden ------------------------------
__global__ void final_kernel(const __half* __restrict__ hhi,  // (128,256)
                             const __half* __restrict__ hlo,
                             const float* __restrict__ Wsm,
                             const float* __restrict__ bs,
                             float* __restrict__ out, int out_size) {
    int b = blockIdx.x;
    int t = threadIdx.x;
    __shared__ float hs[512];
    for (int jj = t; jj < 512; jj += 256) {
        float v = __half2float(hhi[b * 512 + jj]) + __half2float(hlo[b * 512 + jj]);
        hs[jj] = v;
        if (out_size >= 192 + 64 * 512) out[192 + b * 512 + jj] = v;
    }
    __syncthreads();
    if (t < 3) {
        float s = bs[t];
        for (int jj = 0; jj < 512; jj++) s += hs[jj] * Wsm[jj * 3 + t];
        out[b * 3 + t] = s;
    }
}

extern "C" void kernel_launch(void* const* d_in, const int* in_sizes, int n_in,
                              void* d_out, int out_size) {
    const int* node_ids = (const int*)d_in[0];
    const float* emb = (const float*)d_in[1];
    const float* W = (const float*)d_in[2];
    const float* bW = (const float*)d_in[3];
    const float* U = (const float*)d_in[4];
    const float* Ws = (const float*)d_in[5];
    const float* bs = (const float*)d_in[6];
    float* out = (float*)d_out;

    __half *hhi0, *hlo0, *hhi1, *hlo1;
    float *c0, *c1;
    cudaGetSymbolAddress((void**)&hhi0, g_hhi0);
    cudaGetSymbolAddress((void**)&hlo0, g_hlo0);
    cudaGetSymbolAddress((void**)&c0, g_c0);
    cudaGetSymbolAddress((void**)&hhi1, g_hhi1);
    cudaGetSymbolAddress((void**)&hlo1, g_hlo1);
    cudaGetSymbolAddress((void**)&c1, g_c1);

    cudaFuncSetAttribute(mma_level_kernel<128>,
                         cudaFuncAttributeMaxDynamicSharedMemorySize, SMEM_REQ);
    cudaFuncSetAttribute(mma_level_kernel<32>,
                         cudaFuncAttributeMaxDynamicSharedMemorySize, SMEM_REQ);

    prep1_kernel<<<64, 256>>>(emb, W, bW);
    prep2_kernel<<<dim3(64, 2), 256>>>(U);
    prep3_kernel<<<640, 1024>>>(U);

    level9_kernel<<<32768, 256>>>(node_ids, hhi0, hlo0, c0);

    __half *hip = hhi0, *lop = hlo0, *hic = hhi1, *loc = hlo1;
    float *cp = c0, *cc = c1;
    for (int lev = 8; lev >= 1; lev--) {
        int rows = 64 << lev;
        if (lev >= 7) {
            dim3 grid(rows / 128, 4);
            mma_level_kernel<128><<<grid, 256, SMEM_REQ>>>(hip, lop, cp, node_ids,
                                                           hic, loc, cc, lev);
        } else {
            dim3 grid(rows / 32, 4);
            mma_level_kernel<32><<<grid, 256, SMEM_REQ>>>(hip, lop, cp, node_ids,
                                                          hic, loc, cc, lev);
        }
        __half* t;
        t = hip; hip = hic; hic = t;
        t = lop; lop = loc; loc = t;
        float* t2 = cp; cp = cc; cc = t2;
    }
    final_kernel<<<64, 256>>>(hip, lop, Ws, bs, out, out_size);
}

// round 9
// speedup vs baseline: 2.8157x; 1.4003x over previous
#include <cuda_runtime.h>
#include <cuda_fp16.h>
#include <cstdint>

// TreeLSTM B=64, L=10, H=E=256, V=64, TOTAL=2046.
//  - Gtab/Htab/Ctab tabulated per vocab id; level-9 U-GEMM tabulated (TL/TR)
//  - levels 8..1: mma.sync fp16 single-pass (A,B rounded to fp16, fp32 accum)
//    fused with LSTM gating epilogue. K-chunks of 64, 3-stage cp.async pipeline.
//  - lev-1 epilogue writes fp32 h for exact root_hidden/scores.

#define TOTAL_NODES 2046

// ---------------- scratch ----------------
__device__ __half g_h0[32768 * 256];
__device__ float  g_c0[32768 * 256];
__device__ __half g_h1[16384 * 256];
__device__ float  g_c1[16384 * 256];
__device__ float  g_hroot[128 * 256];    // fp32 h at level 1
__device__ float g_Gtab[64 * 4 * 256];
__device__ float g_Htab[64 * 256];
__device__ float g_Ctab[64 * 256];
__device__ float g_TL[64 * 5 * 256];
__device__ float g_TR[64 * 5 * 256];
__device__ __half g_Bh[5 * 256 * 512];   // [g][n][k]  k = s*256+h, fp16 rounded

// ---------------- helpers ----------------
__device__ __forceinline__ float ftanh(float x) {
    float y; asm("tanh.approx.f32 %0, %1;" : "=f"(y) : "f"(x)); return y;
}
__device__ __forceinline__ float fsig(float x) { return 0.5f * ftanh(0.5f * x) + 0.5f; }

__device__ __forceinline__ uint32_t smem_u32(const void* p) {
    uint32_t a;
    asm("{ .reg .u64 t; cvta.to.shared.u64 t, %1; cvt.u32.u64 %0, t; }" : "=r"(a) : "l"(p));
    return a;
}

#define CP_ASYNC16(dst, src) \
    asm volatile("cp.async.cg.shared.global [%0], [%1], 16;" :: "r"(dst), "l"(src) : "memory")
#define CP_COMMIT() asm volatile("cp.async.commit_group;" ::: "memory")
#define CP_WAIT2()  asm volatile("cp.async.wait_group 2;" ::: "memory")

#define LDSM4(r, a) \
    asm volatile("ldmatrix.sync.aligned.m8n8.x4.shared.b16 {%0,%1,%2,%3}, [%4];" \
        : "=r"((r)[0]), "=r"((r)[1]), "=r"((r)[2]), "=r"((r)[3]) : "r"(a))

#define MMA16816(c, a, b0, b1) \
    asm volatile("mma.sync.aligned.m16n8k16.row.col.f32.f16.f16.f32 " \
        "{%0,%1,%2,%3}, {%4,%5,%6,%7}, {%8,%9}, {%0,%1,%2,%3};" \
        : "+f"((c)[0]), "+f"((c)[1]), "+f"((c)[2]), "+f"((c)[3]) \
        : "r"((a)[0]), "r"((a)[1]), "r"((a)[2]), "r"((a)[3]), "r"(b0), "r"(b1))

// ---------------- prep 1: Gtab, Htab, Ctab --------------------------------
__global__ void prep1_kernel(const float* __restrict__ emb,
                             const float* __restrict__ W,
                             const float* __restrict__ bW) {
    int v = blockIdx.x;
    int h = threadIdx.x;
    __shared__ float e[256];
    e[h] = emb[v * 256 + h];
    __syncthreads();
    float xg[4];
#pragma unroll
    for (int g = 0; g < 4; g++) {
        float s = bW[g * 256 + h];
        const float* Wg = W + g * 256 * 256 + h;
        for (int k = 0; k < 256; k++) s += e[k] * Wg[k * 256];
        xg[g] = s;
        g_Gtab[v * 1024 + g * 256 + h] = s;
    }
    float ig = fsig(xg[1]);
    float og = fsig(xg[2]);
    float ug = ftanh(xg[3]);
    float cc = ig * ug;
    g_Ctab[v * 256 + h] = cc;
    g_Htab[v * 256 + h] = og * ftanh(cc);
}

// ---------------- prep 2: TL/TR ------------------------------------------
__global__ void prep2_kernel(const float* __restrict__ U) {
    int v = blockIdx.x;
    int s = blockIdx.y;
    int k = threadIdx.x;
    __shared__ float hh[256];
    hh[k] = g_Htab[v * 256 + k];
    __syncthreads();
    float* T = (s == 0) ? g_TL : g_TR;
#pragma unroll
    for (int g = 0; g < 5; g++) {
        float acc = 0.0f;
        const float* Ug = U + ((g * 2 + s) * 256) * 256 + k;
        for (int h = 0; h < 256; h++) acc += hh[h] * Ug[h * 256];
        T[v * 1280 + g * 256 + k] = acc;
    }
}

// ---------------- prep 3: B fp16 plane [g][n][k] ---------------------------
__global__ void prep3_kernel(const float* __restrict__ U) {
    int idx = blockIdx.x * blockDim.x + threadIdx.x;  // 5*256*512 = 655360
    if (idx >= 5 * 256 * 512) return;
    int k = idx & 511;
    int n = (idx >> 9) & 255;
    int g = idx >> 17;
    int s = k >> 8;
    int h = k & 255;
    g_Bh[idx] = __float2half_rn(U[((g * 2 + s) * 256 + h) * 256 + n]);
}

// ---------------- level 9: gather + gating --------------------------------
__global__ void level9_kernel(const int* __restrict__ node_ids,
                              __half* __restrict__ hout,
                              float* __restrict__ cout) {
    int row = blockIdx.x;
    int j = threadIdx.x;
    int bb = row >> 9;
    int jn = row & 511;
    const int* nr = node_ids + bb * TOTAL_NODES;
    int id  = nr[510 + jn];
    int idL = nr[1022 + 2 * jn];
    int idR = nr[1023 + 2 * jn];
    const float* tl = g_TL + idL * 1280;
    const float* tr = g_TR + idR * 1280;
    const float* gt = g_Gtab + id * 1024;
    float p0 = tl[j]        + tr[j]        + gt[j];
    float p1 = tl[256 + j]  + tr[256 + j]  + gt[j];
    float p2 = tl[512 + j]  + tr[512 + j]  + gt[256 + j];
    float p3 = tl[768 + j]  + tr[768 + j]  + gt[512 + j];
    float p4 = tl[1024 + j] + tr[1024 + j] + gt[768 + j];
    float cl = g_Ctab[idL * 256 + j];
    float cr = g_Ctab[idR * 256 + j];
    float cc = fsig(p2) * ftanh(p4) + fsig(p0) * cl + fsig(p1) * cr;
    cout[row * 256 + j] = cc;
    hout[row * 256 + j] = __float2half_rn(fsig(p3) * ftanh(cc));
}

// ---------------- mma.sync level kernel (levels 8..1) ----------------------
// CTA: CM rows x (5 gates x 64 j = 320 N), K=512 in 8 chunks of 64.
// 8 warps (2 x 4), warp tile (CM/2) x 80. Single-pass fp16.
// SMEM stage: A[CM][72] B[320][72] fp16 (144B rows), 3 stages.
template <int CM>
__global__ void __launch_bounds__(256, 1)
mma_level_kernel(const __half* __restrict__ A_g,    // (rows,512) view
                 const float* __restrict__ c_prev,   // (rows,512) view
                 const int* __restrict__ node_ids,
                 __half* __restrict__ h_out,
                 float* __restrict__ c_out,
                 int lev) {
    constexpr int WM = CM / 2;          // warp tile M
    constexpr int NI = WM / 16;         // m16 fragments per warp
    constexpr int OFF_B = CM * 144;
    constexpr int STG   = (CM + 320) * 144;
    constexpr int ACPT  = (CM * 8) / 256;   // A cp.async per thread

    extern __shared__ __align__(128) char dsm[];
    const uint32_t sbase = smem_u32(dsm);

    const int rbase = blockIdx.x * CM;
    const int jbase = blockIdx.y * 64;
    const int tid = threadIdx.x;
    const int wid = tid >> 5;
    const int lid = tid & 31;
    const int wr = wid >> 2;       // warp row (0..1): m0 = wr*WM
    const int wc = wid & 3;        // warp col (0..3): n0 = wc*80

    float acc[NI][10][4];
#pragma unroll
    for (int i = 0; i < NI; i++)
#pragma unroll
        for (int j = 0; j < 10; j++)
#pragma unroll
            for (int e = 0; e < 4; e++) acc[i][j][e] = 0.0f;

    const uint32_t a_lane = (uint32_t)((lid & 15) * 144 + (lid >> 4) * 16);
    const uint32_t b_lane = (uint32_t)(((lid & 7) + (lid >> 4) * 8) * 144 + ((lid >> 3) & 1) * 16);

    auto load_chunk = [&](int kc, int st) {
        const uint32_t S = sbase + st * STG;
        const int k0 = kc * 64;
        // A: CM rows x 8 segs(16B)
#pragma unroll
        for (int i = 0; i < ACPT; i++) {
            int c = i * 256 + tid;
            int r = c >> 3;
            int sg = c & 7;
            const __half* src = A_g + (size_t)(rbase + r) * 512 + k0 + sg * 8;
            CP_ASYNC16(S + r * 144 + sg * 16, src);
        }
        // B: 320 n x 8 segs = 2560 copies, 10/thread
#pragma unroll
        for (int i = 0; i < 10; i++) {
            int c = i * 256 + tid;
            int n = c >> 3;
            int sg = c & 7;
            int g = n >> 6;
            int jj = n & 63;
            const __half* src = g_Bh + (size_t)(g * 256 + jbase + jj) * 512 + k0 + sg * 8;
            CP_ASYNC16(S + OFF_B + n * 144 + sg * 16, src);
        }
    };

    load_chunk(0, 0); CP_COMMIT();
    load_chunk(1, 1); CP_COMMIT();

    for (int kc = 0; kc < 8; kc++) {
        if (kc + 2 < 8) load_chunk(kc + 2, (kc + 2) % 3);
        CP_COMMIT();
        CP_WAIT2();
        __syncthreads();

        const uint32_t S = sbase + (kc % 3) * STG;
        const uint32_t sA = S + wr * (WM * 144) + a_lane;
        const uint32_t sB = S + OFF_B + wc * (80 * 144) + b_lane;

#pragma unroll
        for (int kk = 0; kk < 4; kk++) {
            const uint32_t ko = kk * 32;
            uint32_t am[NI][4], bm[5][4];
#pragma unroll
            for (int i = 0; i < NI; i++) LDSM4(am[i], sA + i * (16 * 144) + ko);
#pragma unroll
            for (int jp = 0; jp < 5; jp++) LDSM4(bm[jp], sB + jp * (16 * 144) + ko);
#pragma unroll
            for (int i = 0; i < NI; i++)
#pragma unroll
                for (int jp = 0; jp < 5; jp++) {
                    MMA16816(acc[i][2 * jp],     am[i], bm[jp][0], bm[jp][1]);
                    MMA16816(acc[i][2 * jp + 1], am[i], bm[jp][2], bm[jp][3]);
                }
        }
        __syncthreads();
    }

    // ---- epilogue: C -> smem, gate, store ----
    float* Csm = (float*)dsm;            // [CM][328]
    __shared__ int s_id[CM];
    const int n = 1 << lev;
    const int off = n - 2;
    if (tid < CM) {
        int row = rbase + tid;
        int bb = row >> lev;
        int jn = row & (n - 1);
        s_id[tid] = node_ids[bb * TOTAL_NODES + off + jn];
    }
    {
        const int m0 = wr * WM;
        const int n0 = wc * 80;
        const int mr = lid >> 2;
        const int nc = (lid & 3) * 2;
#pragma unroll
        for (int i = 0; i < NI; i++)
#pragma unroll
            for (int j = 0; j < 10; j++) {
                int m = m0 + i * 16 + mr;
                int nn = n0 + j * 8 + nc;
                *(float2*)&Csm[m * 328 + nn] = make_float2(acc[i][j][0], acc[i][j][1]);
                *(float2*)&Csm[(m + 8) * 328 + nn] = make_float2(acc[i][j][2], acc[i][j][3]);
            }
    }
    __syncthreads();

    const int j = tid & 63;
    const int jg = jbase + j;
#pragma unroll 4
    for (int m = (tid >> 6); m < CM; m += 4) {
        const float* gt = g_Gtab + s_id[m] * 1024;
        const float* Cr = Csm + m * 328 + j;
        int row = rbase + m;
        float p0 = Cr[0]   + gt[jg];
        float p1 = Cr[64]  + gt[jg];
        float p2 = Cr[128] + gt[256 + jg];
        float p3 = Cr[192] + gt[512 + jg];
        float p4 = Cr[256] + gt[768 + jg];
        float cl = c_prev[(size_t)row * 512 + jg];
        float cr = c_prev[(size_t)row * 512 + 256 + jg];
        float cc = fsig(p2) * ftanh(p4) + fsig(p0) * cl + fsig(p1) * cr;
        float hh = fsig(p3) * ftanh(cc);
        size_t o = (size_t)row * 256 + jg;
        c_out[o] = cc;
        h_out[o] = __float2half_rn(hh);
        if (lev == 1) g_hroot[o] = hh;   // exact fp32 h for root outputs
    }
}

// ---------------- final: scores + root_hidden ------------------------------
__global__ void final_kernel(const float* __restrict__ Wsm,
                             const float* __restrict__ bs,
                             float* __restrict__ out, int out_size) {
    int b = blockIdx.x;
    int t = threadIdx.x;
    __shared__ float hs[512];
    for (int jj = t; jj < 512; jj += 256) {
        float v = g_hroot[b * 512 + jj];
        hs[jj] = v;
        if (out_size >= 192 + 64 * 512) out[192 + b * 512 + jj] = v;
    }
    __syncthreads();
    if (t < 3) {
        float s = bs[t];
        for (int jj = 0; jj < 512; jj++) s += hs[jj] * Wsm[jj * 3 + t];
        out[b * 3 + t] = s;
    }
}

#define SMEM_128 ((128 + 320) * 144 * 3)
#define SMEM_32  ((32 + 320) * 144 * 3)

extern "C" void kernel_launch(void* const* d_in, const int* in_sizes, int n_in,
                              void* d_out, int out_size) {
    const int* node_ids = (const int*)d_in[0];
    const float* emb = (const float*)d_in[1];
    const float* W = (const float*)d_in[2];
    const float* bW = (const float*)d_in[3];
    const float* U = (const float*)d_in[4];
    const float* Ws = (const float*)d_in[5];
    const float* bs = (const float*)d_in[6];
    float* out = (float*)d_out;

    __half *h0, *h1;
    float *c0, *c1;
    cudaGetSymbolAddress((void**)&h0, g_h0);
    cudaGetSymbolAddress((void**)&c0, g_c0);
    cudaGetSymbolAddress((void**)&h1, g_h1);
    cudaGetSymbolAddress((void**)&c1, g_c1);

    cudaFuncSetAttribute(mma_level_kernel<128>,
                         cudaFuncAttributeMaxDynamicSharedMemorySize, SMEM_128);
    cudaFuncSetAttribute(mma_level_kernel<32>,
                         cudaFuncAttributeMaxDynamicSharedMemorySize, SMEM_32);

    prep1_kernel<<<64, 256>>>(emb, W, bW);
    prep2_kernel<<<dim3(64, 2), 256>>>(U);
    prep3_kernel<<<640, 1024>>>(U);

    level9_kernel<<<32768, 256>>>(node_ids, h0, c0);

    __half *hp = h0, *hc = h1;
    float *cp = c0, *cc = c1;
    for (int lev = 8; lev >= 1; lev--) {
        int rows = 64 << lev;
        if (lev >= 7) {
            dim3 grid(rows / 128, 4);
            mma_level_kernel<128><<<grid, 256, SMEM_128>>>(hp, cp, node_ids, hc, cc, lev);
        } else {
            dim3 grid(rows / 32, 4);
            mma_level_kernel<32><<<grid, 256, SMEM_32>>>(hp, cp, node_ids, hc, cc, lev);
        }
        __half* t1 = hp; hp = hc; hc = t1;
        float* t2 = cp; cp = cc; cc = t2;
    }
    final_kernel<<<64, 256>>>(Ws, bs, out, out_size);
}

// round 11
// speedup vs baseline: 3.3116x; 1.1761x over previous
#include <cuda_runtime.h>
#include <cuda_fp16.h>
#include <cstdint>

// TreeLSTM B=64, L=10, H=E=256, V=64, TOTAL=2046.
//  - Gtab/Htab/Ctab tabulated per vocab id; level-9 U-GEMM tabulated (TL/TR)
//  - levels 8..1: mma.sync fp16 single-pass, register-only gating epilogue
//    (B gate-separate so all 5 gates of one (m,j) live in one thread),
//    2 CTAs/SM (96KB stages, XOR-swizzled 128B rows, 2-stage cp.async).

#define TOTAL_NODES 2046

// ---------------- scratch ----------------
__device__ __half g_h0[32768 * 256];
__device__ float  g_c0[32768 * 256];
__device__ __half g_h1[16384 * 256];
__device__ float  g_c1[16384 * 256];
__device__ float  g_hroot[128 * 256];    // fp32 h at level 1
__device__ float g_Gtab[64 * 4 * 256];
__device__ float g_Htab[64 * 256];
__device__ float g_Ctab[64 * 256];
__device__ float g_TL[64 * 5 * 256];
__device__ float g_TR[64 * 5 * 256];
__device__ __half g_Bh[5 * 256 * 512];   // [g][n][k]  k = s*256+h, fp16 rounded

// ---------------- helpers ----------------
__device__ __forceinline__ float ftanh(float x) {
    float y; asm("tanh.approx.f32 %0, %1;" : "=f"(y) : "f"(x)); return y;
}
__device__ __forceinline__ float fsig(float x) { return 0.5f * ftanh(0.5f * x) + 0.5f; }

__device__ __forceinline__ uint32_t smem_u32(const void* p) {
    uint32_t a;
    asm("{ .reg .u64 t; cvta.to.shared.u64 t, %1; cvt.u32.u64 %0, t; }" : "=r"(a) : "l"(p));
    return a;
}

#define CP_ASYNC16(dst, src) \
    asm volatile("cp.async.cg.shared.global [%0], [%1], 16;" :: "r"(dst), "l"(src) : "memory")
#define CP_COMMIT() asm volatile("cp.async.commit_group;" ::: "memory")
#define CP_WAIT1()  asm volatile("cp.async.wait_group 1;" ::: "memory")

#define LDSM4(r, a) \
    asm volatile("ldmatrix.sync.aligned.m8n8.x4.shared.b16 {%0,%1,%2,%3}, [%4];" \
        : "=r"((r)[0]), "=r"((r)[1]), "=r"((r)[2]), "=r"((r)[3]) : "r"(a))

#define MMA16816(c, a, b0, b1) \
    asm volatile("mma.sync.aligned.m16n8k16.row.col.f32.f16.f16.f32 " \
        "{%0,%1,%2,%3}, {%4,%5,%6,%7}, {%8,%9}, {%0,%1,%2,%3};" \
        : "+f"((c)[0]), "+f"((c)[1]), "+f"((c)[2]), "+f"((c)[3]) \
        : "r"((a)[0]), "r"((a)[1]), "r"((a)[2]), "r"((a)[3]), "r"(b0), "r"(b1))

// ---------------- prep 1: Gtab, Htab, Ctab --------------------------------
__global__ void prep1_kernel(const float* __restrict__ emb,
                             const float* __restrict__ W,
                             const float* __restrict__ bW) {
    int v = blockIdx.x;
    int h = threadIdx.x;
    __shared__ float e[256];
    e[h] = emb[v * 256 + h];
    __syncthreads();
    float xg[4];
#pragma unroll
    for (int g = 0; g < 4; g++) {
        float s = bW[g * 256 + h];
        const float* Wg = W + g * 256 * 256 + h;
        for (int k = 0; k < 256; k++) s += e[k] * Wg[k * 256];
        xg[g] = s;
        g_Gtab[v * 1024 + g * 256 + h] = s;
    }
    float ig = fsig(xg[1]);
    float og = fsig(xg[2]);
    float ug = ftanh(xg[3]);
    float cc = ig * ug;
    g_Ctab[v * 256 + h] = cc;
    g_Htab[v * 256 + h] = og * ftanh(cc);
}

// ---------------- prep 2: TL/TR ------------------------------------------
__global__ void prep2_kernel(const float* __restrict__ U) {
    int v = blockIdx.x;
    int s = blockIdx.y;
    int k = threadIdx.x;
    __shared__ float hh[256];
    hh[k] = g_Htab[v * 256 + k];
    __syncthreads();
    float* T = (s == 0) ? g_TL : g_TR;
#pragma unroll
    for (int g = 0; g < 5; g++) {
        float acc = 0.0f;
        const float* Ug = U + ((g * 2 + s) * 256) * 256 + k;
        for (int h = 0; h < 256; h++) acc += hh[h] * Ug[h * 256];
        T[v * 1280 + g * 256 + k] = acc;
    }
}

// ---------------- prep 3: B fp16 plane [g][n][k] ---------------------------
__global__ void prep3_kernel(const float* __restrict__ U) {
    int idx = blockIdx.x * blockDim.x + threadIdx.x;  // 5*256*512 = 655360
    if (idx >= 5 * 256 * 512) return;
    int k = idx & 511;
    int n = (idx >> 9) & 255;
    int g = idx >> 17;
    int s = k >> 8;
    int h = k & 255;
    g_Bh[idx] = __float2half_rn(U[((g * 2 + s) * 256 + h) * 256 + n]);
}

// ---------------- level 9: gather + gating --------------------------------
__global__ void level9_kernel(const int* __restrict__ node_ids,
                              __half* __restrict__ hout,
                              float* __restrict__ cout) {
    int row = blockIdx.x;
    int j = threadIdx.x;
    int bb = row >> 9;
    int jn = row & 511;
    const int* nr = node_ids + bb * TOTAL_NODES;
    int id  = nr[510 + jn];
    int idL = nr[1022 + 2 * jn];
    int idR = nr[1023 + 2 * jn];
    const float* tl = g_TL + idL * 1280;
    const float* tr = g_TR + idR * 1280;
    const float* gt = g_Gtab + id * 1024;
    float p0 = tl[j]        + tr[j]        + gt[j];
    float p1 = tl[256 + j]  + tr[256 + j]  + gt[j];
    float p2 = tl[512 + j]  + tr[512 + j]  + gt[256 + j];
    float p3 = tl[768 + j]  + tr[768 + j]  + gt[512 + j];
    float p4 = tl[1024 + j] + tr[1024 + j] + gt[768 + j];
    float cl = g_Ctab[idL * 256 + j];
    float cr = g_Ctab[idR * 256 + j];
    float cc = fsig(p2) * ftanh(p4) + fsig(p0) * cl + fsig(p1) * cr;
    cout[row * 256 + j] = cc;
    hout[row * 256 + j] = __float2half_rn(fsig(p3) * ftanh(cc));
}

// ---------------- mma.sync level kernel (levels 8..1) ----------------------
// CTA: 64 rows x 64 j x 5 gates, K=512 in 8 chunks of 64. 128 threads.
// 4 warps (wc = warp id), each: 64m x 16j x 5 gates. NI=4 m-frags.
// SMEM stage: A[64][128B] B[320][128B], XOR seg-swizzle, 2 stages (96KB).
// Epilogue: all 5 gates of (m,j) in-thread -> register gating, direct stores.
#define OFF_B 8192
#define STG   49152
#define SMEM_MMA (2 * STG)

__global__ void __launch_bounds__(128, 2)
mma_level_kernel(const __half* __restrict__ A_g,    // (rows,512) view
                 const float* __restrict__ c_prev,   // (rows,512) view
                 const int* __restrict__ node_ids,
                 __half* __restrict__ h_out,
                 float* __restrict__ c_out,
                 int lev) {
    extern __shared__ __align__(128) char dsm[];
    const uint32_t sbase = smem_u32(dsm);

    const int rbase = blockIdx.x * 64;
    const int jbase = blockIdx.y * 64;
    const int tid = threadIdx.x;
    const int wc = tid >> 5;       // warp col 0..3 (16-j slice)
    const int lid = tid & 31;

    float acc[4][5][2][4];
#pragma unroll
    for (int i = 0; i < 4; i++)
#pragma unroll
        for (int g = 0; g < 5; g++)
#pragma unroll
            for (int u = 0; u < 2; u++)
#pragma unroll
                for (int e = 0; e < 4; e++) acc[i][g][u][e] = 0.0f;

    // ldmatrix lane geometry (same mapping as validated round-7 kernel)
    const int rA = lid & 15;              // A row within 16-frag
    const int hA = lid >> 4;              // A k-half
    const int rB = (lid & 7) + ((lid >> 4) << 3);   // B row within 16
    const int hB = (lid >> 3) & 1;        // B k-half
    const int rxA = rA & 7;
    const int rxB = rB & 7;

    auto load_chunk = [&](int kc, int st) {
        const uint32_t S = sbase + st * STG;
        const int k0 = kc * 64;
        // A: 64 rows x 8 segs(16B) = 512 copies, 4/thread
#pragma unroll
        for (int i = 0; i < 4; i++) {
            int c = i * 128 + tid;
            int r = c >> 3;
            int sg = c & 7;
            const __half* src = A_g + (size_t)(rbase + r) * 512 + k0 + sg * 8;
            CP_ASYNC16(S + r * 128 + ((sg ^ (r & 7)) << 4), src);
        }
        // B: 320 rows x 8 segs = 2560 copies, 20/thread
#pragma unroll
        for (int i = 0; i < 20; i++) {
            int c = i * 128 + tid;
            int n = c >> 3;
            int sg = c & 7;
            int g = n >> 6;
            int jj = n & 63;
            const __half* src = g_Bh + (size_t)(g * 256 + jbase + jj) * 512 + k0 + sg * 8;
            CP_ASYNC16(S + OFF_B + n * 128 + ((sg ^ (n & 7)) << 4), src);
        }
    };

    load_chunk(0, 0); CP_COMMIT();
    load_chunk(1, 1); CP_COMMIT();

    for (int kc = 0; kc < 8; kc++) {
        CP_WAIT1();
        __syncthreads();
        const uint32_t S = sbase + (kc & 1) * STG;

#pragma unroll
        for (int kk = 0; kk < 4; kk++) {
            uint32_t am[4][4], bm[5][4];
            const int segA = ((kk << 1) + hA) ^ rxA;
            const int segB = ((kk << 1) + hB) ^ rxB;
#pragma unroll
            for (int i = 0; i < 4; i++)
                LDSM4(am[i], S + (i * 16 + rA) * 128 + (segA << 4));
#pragma unroll
            for (int g = 0; g < 5; g++)
                LDSM4(bm[g], S + OFF_B + (g * 64 + wc * 16 + rB) * 128 + (segB << 4));
#pragma unroll
            for (int i = 0; i < 4; i++)
#pragma unroll
                for (int g = 0; g < 5; g++) {
                    MMA16816(acc[i][g][0], am[i], bm[g][0], bm[g][1]);
                    MMA16816(acc[i][g][1], am[i], bm[g][2], bm[g][3]);
                }
        }
        __syncthreads();
        if (kc + 2 < 8) load_chunk(kc + 2, kc & 1);
        CP_COMMIT();
    }

    // ---- register epilogue: gate + direct stores ----
    const int n = 1 << lev;
    const int off = n - 2;
#pragma unroll
    for (int i = 0; i < 4; i++) {
#pragma unroll
        for (int mh = 0; mh < 2; mh++) {
            int m = i * 16 + (lid >> 2) + mh * 8;
            int row = rbase + m;
            int bb = row >> lev;
            int jn = row & (n - 1);
            int id = node_ids[bb * TOTAL_NODES + off + jn];
            const float* gt = g_Gtab + id * 1024;
#pragma unroll
            for (int u = 0; u < 2; u++) {
                int j = wc * 16 + u * 8 + (lid & 3) * 2;
                int jg = jbase + j;
                float2 g0 = *(const float2*)(gt + jg);
                float2 g1 = *(const float2*)(gt + 256 + jg);
                float2 g2 = *(const float2*)(gt + 512 + jg);
                float2 g3 = *(const float2*)(gt + 768 + jg);
                float2 cl = *(const float2*)(c_prev + (size_t)row * 512 + jg);
                float2 cr = *(const float2*)(c_prev + (size_t)row * 512 + 256 + jg);
                float p0x = acc[i][0][u][mh * 2 + 0] + g0.x;
                float p0y = acc[i][0][u][mh * 2 + 1] + g0.y;
                float p1x = acc[i][1][u][mh * 2 + 0] + g0.x;
                float p1y = acc[i][1][u][mh * 2 + 1] + g0.y;
                float p2x = acc[i][2][u][mh * 2 + 0] + g1.x;
                float p2y = acc[i][2][u][mh * 2 + 1] + g1.y;
                float p3x = acc[i][3][u][mh * 2 + 0] + g2.x;
                float p3y = acc[i][3][u][mh * 2 + 1] + g2.y;
                float p4x = acc[i][4][u][mh * 2 + 0] + g3.x;
                float p4y = acc[i][4][u][mh * 2 + 1] + g3.y;
                float2 cc;
                cc.x = fsig(p2x) * ftanh(p4x) + fsig(p0x) * cl.x + fsig(p1x) * cr.x;
                cc.y = fsig(p2y) * ftanh(p4y) + fsig(p0y) * cl.y + fsig(p1y) * cr.y;
                float hx = fsig(p3x) * ftanh(cc.x);
                float hy = fsig(p3y) * ftanh(cc.y);
                size_t o = (size_t)row * 256 + jg;
                *(float2*)(c_out + o) = cc;
                *(__half2*)(h_out + o) = __floats2half2_rn(hx, hy);
                if (lev == 1) *(float2*)(g_hroot + o) = make_float2(hx, hy);
            }
        }
    }
}

// ---------------- final: scores + root_hidden ------------------------------
__global__ void final_kernel(const float* __restrict__ Wsm,
                             const float* __restrict__ bs,
                             float* __restrict__ out, int out_size) {
    int b = blockIdx.x;
    int t = threadIdx.x;
    __shared__ float hs[512];
    for (int jj = t; jj < 512; jj += 256) {
        float v = g_hroot[b * 512 + jj];
        hs[jj] = v;
        if (out_size >= 192 + 64 * 512) out[192 + b * 512 + jj] = v;
    }
    __syncthreads();
    if (t < 3) {
        float s = bs[t];
        for (int jj = 0; jj < 512; jj++) s += hs[jj] * Wsm[jj * 3 + t];
        out[b * 3 + t] = s;
    }
}

extern "C" void kernel_launch(void* const* d_in, const int* in_sizes, int n_in,
                              void* d_out, int out_size) {
    const int* node_ids = (const int*)d_in[0];
    const float* emb = (const float*)d_in[1];
    const float* W = (const float*)d_in[2];
    const float* bW = (const float*)d_in[3];
    const float* U = (const float*)d_in[4];
    const float* Ws = (const float*)d_in[5];
    const float* bs = (const float*)d_in[6];
    float* out = (float*)d_out;

    __half *h0, *h1;
    float *c0, *c1;
    cudaGetSymbolAddress((void**)&h0, g_h0);
    cudaGetSymbolAddress((void**)&c0, g_c0);
    cudaGetSymbolAddress((void**)&h1, g_h1);
    cudaGetSymbolAddress((void**)&c1, g_c1);

    cudaFuncSetAttribute(mma_level_kernel,
                         cudaFuncAttributeMaxDynamicSharedMemorySize, SMEM_MMA);

    prep1_kernel<<<64, 256>>>(emb, W, bW);
    prep2_kernel<<<dim3(64, 2), 256>>>(U);
    prep3_kernel<<<640, 1024>>>(U);

    level9_kernel<<<32768, 256>>>(node_ids, h0, c0);

    __half *hp = h0, *hc = h1;
    float *cp = c0, *cc = c1;
    for (int lev = 8; lev >= 1; lev--) {
        int rows = 64 << lev;
        dim3 grid(rows / 64, 4);
        mma_level_kernel<<<grid, 128, SMEM_MMA>>>(hp, cp, node_ids, hc, cc, lev);
        __half* t1 = hp; hp = hc; hc = t1;
        float* t2 = cp; cp = cc; cc = t2;
    }
    final_kernel<<<64, 256>>>(Ws, bs, out, out_size);
}

// round 12
// speedup vs baseline: 3.5371x; 1.0681x over previous
#include <cuda_runtime.h>
#include <cuda_fp16.h>
#include <cstdint>

// TreeLSTM B=64, L=10, H=E=256, V=64, TOTAL=2046.
//  - Gtab/Htab/Ctab tabulated per vocab id; level-9 U-GEMM tabulated (TL/TR)
//  - levels 8..1: mma.sync fp16 single-pass, register-only gating epilogue.
//    CM=128 x (5 gates x 64 j), 256 threads, 4-stage cp.async ring (1 sync/chunk).

#define TOTAL_NODES 2046

// ---------------- scratch ----------------
__device__ __half g_h0[32768 * 256];
__device__ float  g_c0[32768 * 256];
__device__ __half g_h1[16384 * 256];
__device__ float  g_c1[16384 * 256];
__device__ float  g_hroot[128 * 256];    // fp32 h at level 1
__device__ float g_Gtab[64 * 4 * 256];
__device__ float g_Htab[64 * 256];
__device__ float g_Ctab[64 * 256];
__device__ float g_TL[64 * 5 * 256];
__device__ float g_TR[64 * 5 * 256];
__device__ __half g_Bh[5 * 256 * 512];   // [g][n][k]  k = s*256+h, fp16 rounded

// ---------------- helpers ----------------
__device__ __forceinline__ float ftanh(float x) {
    float y; asm("tanh.approx.f32 %0, %1;" : "=f"(y) : "f"(x)); return y;
}
__device__ __forceinline__ float fsig(float x) { return 0.5f * ftanh(0.5f * x) + 0.5f; }

__device__ __forceinline__ uint32_t smem_u32(const void* p) {
    uint32_t a;
    asm("{ .reg .u64 t; cvta.to.shared.u64 t, %1; cvt.u32.u64 %0, t; }" : "=r"(a) : "l"(p));
    return a;
}

#define CP_ASYNC16(dst, src) \
    asm volatile("cp.async.cg.shared.global [%0], [%1], 16;" :: "r"(dst), "l"(src) : "memory")
#define CP_COMMIT() asm volatile("cp.async.commit_group;" ::: "memory")
#define CP_WAIT2()  asm volatile("cp.async.wait_group 2;" ::: "memory")

#define LDSM4(r, a) \
    asm volatile("ldmatrix.sync.aligned.m8n8.x4.shared.b16 {%0,%1,%2,%3}, [%4];" \
        : "=r"((r)[0]), "=r"((r)[1]), "=r"((r)[2]), "=r"((r)[3]) : "r"(a))

#define MMA16816(c, a, b0, b1) \
    asm volatile("mma.sync.aligned.m16n8k16.row.col.f32.f16.f16.f32 " \
        "{%0,%1,%2,%3}, {%4,%5,%6,%7}, {%8,%9}, {%0,%1,%2,%3};" \
        : "+f"((c)[0]), "+f"((c)[1]), "+f"((c)[2]), "+f"((c)[3]) \
        : "r"((a)[0]), "r"((a)[1]), "r"((a)[2]), "r"((a)[3]), "r"(b0), "r"(b1))

// ---------------- prep 1: Gtab, Htab, Ctab --------------------------------
__global__ void prep1_kernel(const float* __restrict__ emb,
                             const float* __restrict__ W,
                             const float* __restrict__ bW) {
    int v = blockIdx.x;
    int h = threadIdx.x;
    __shared__ float e[256];
    e[h] = emb[v * 256 + h];
    __syncthreads();
    float xg[4];
#pragma unroll
    for (int g = 0; g < 4; g++) {
        float s = bW[g * 256 + h];
        const float* Wg = W + g * 256 * 256 + h;
        for (int k = 0; k < 256; k++) s += e[k] * Wg[k * 256];
        xg[g] = s;
        g_Gtab[v * 1024 + g * 256 + h] = s;
    }
    float ig = fsig(xg[1]);
    float og = fsig(xg[2]);
    float ug = ftanh(xg[3]);
    float cc = ig * ug;
    g_Ctab[v * 256 + h] = cc;
    g_Htab[v * 256 + h] = og * ftanh(cc);
}

// ---------------- prep 2: TL/TR  (grid (64,10): v x (g,s)) -----------------
__global__ void prep2_kernel(const float* __restrict__ U) {
    int v = blockIdx.x;
    int g = blockIdx.y >> 1;
    int s = blockIdx.y & 1;
    int k = threadIdx.x;
    __shared__ float hh[256];
    hh[k] = g_Htab[v * 256 + k];
    __syncthreads();
    float* T = (s == 0) ? g_TL : g_TR;
    float acc = 0.0f;
    const float* Ug = U + ((g * 2 + s) * 256) * 256 + k;
    for (int h = 0; h < 256; h++) acc += hh[h] * Ug[h * 256];
    T[v * 1280 + g * 256 + k] = acc;
}

// ---------------- prep 3: B fp16 plane [g][n][k] ---------------------------
__global__ void prep3_kernel(const float* __restrict__ U) {
    int idx = blockIdx.x * blockDim.x + threadIdx.x;  // 5*256*512 = 655360
    if (idx >= 5 * 256 * 512) return;
    int k = idx & 511;
    int n = (idx >> 9) & 255;
    int g = idx >> 17;
    int s = k >> 8;
    int h = k & 255;
    g_Bh[idx] = __float2half_rn(U[((g * 2 + s) * 256 + h) * 256 + n]);
}

// ---------------- level 9: gather + gating (float4, 4 rows/block) ----------
__global__ void level9_kernel(const int* __restrict__ node_ids,
                              __half* __restrict__ hout,
                              float* __restrict__ cout) {
    int t = threadIdx.x;
    int row = blockIdx.x * 4 + (t >> 6);       // 4 rows per 256-thread block
    int jq = (t & 63);                          // float4 group: j = jq*4..jq*4+3
    int bb = row >> 9;
    int jn = row & 511;
    const int* nr = node_ids + bb * TOTAL_NODES;
    int id  = nr[510 + jn];
    int idL = nr[1022 + 2 * jn];
    int idR = nr[1023 + 2 * jn];
    const float* tl = g_TL + idL * 1280 + jq * 4;
    const float* tr = g_TR + idR * 1280 + jq * 4;
    const float* gt = g_Gtab + id * 1024 + jq * 4;
    float4 t0l = *(const float4*)(tl);
    float4 t1l = *(const float4*)(tl + 256);
    float4 t2l = *(const float4*)(tl + 512);
    float4 t3l = *(const float4*)(tl + 768);
    float4 t4l = *(const float4*)(tl + 1024);
    float4 t0r = *(const float4*)(tr);
    float4 t1r = *(const float4*)(tr + 256);
    float4 t2r = *(const float4*)(tr + 512);
    float4 t3r = *(const float4*)(tr + 768);
    float4 t4r = *(const float4*)(tr + 1024);
    float4 gg0 = *(const float4*)(gt);
    float4 gg1 = *(const float4*)(gt + 256);
    float4 gg2 = *(const float4*)(gt + 512);
    float4 gg3 = *(const float4*)(gt + 768);
    float4 cl4 = *(const float4*)(g_Ctab + idL * 256 + jq * 4);
    float4 cr4 = *(const float4*)(g_Ctab + idR * 256 + jq * 4);
    float cv[4], hv[4];
#pragma unroll
    for (int e = 0; e < 4; e++) {
        float p0 = ((const float*)&t0l)[e] + ((const float*)&t0r)[e] + ((const float*)&gg0)[e];
        float p1 = ((const float*)&t1l)[e] + ((const float*)&t1r)[e] + ((const float*)&gg0)[e];
        float p2 = ((const float*)&t2l)[e] + ((const float*)&t2r)[e] + ((const float*)&gg1)[e];
        float p3 = ((const float*)&t3l)[e] + ((const float*)&t3r)[e] + ((const float*)&gg2)[e];
        float p4 = ((const float*)&t4l)[e] + ((const float*)&t4r)[e] + ((const float*)&gg3)[e];
        float cl = ((const float*)&cl4)[e];
        float cr = ((const float*)&cr4)[e];
        float cc = fsig(p2) * ftanh(p4) + fsig(p0) * cl + fsig(p1) * cr;
        cv[e] = cc;
        hv[e] = fsig(p3) * ftanh(cc);
    }
    size_t o = (size_t)row * 256 + jq * 4;
    *(float4*)(cout + o) = make_float4(cv[0], cv[1], cv[2], cv[3]);
    __half2 h01 = __floats2half2_rn(hv[0], hv[1]);
    __half2 h23 = __floats2half2_rn(hv[2], hv[3]);
    *(uint2*)(hout + o) = make_uint2(*(uint32_t*)&h01, *(uint32_t*)&h23);
}

// ---------------- mma.sync level kernel (levels 8..1) ----------------------
// CTA: 128 rows x 64 j x 5 gates, K=512 in 8 chunks of 64. 256 threads.
// 8 warps (wr=wid>>2 m-half, wc=wid&3 j-slice); warp: 64m x 16j x 5 gates.
// SMEM stage: A[128][128B] B[320][128B], XOR seg-swizzle, 4-stage ring (224KB).
// One __syncthreads per chunk (write stage (kc+2)%4 never collides with
// slowest warp's read stage (kc+3)%4).
#define OFF_B 16384
#define STG   57344
#define SMEM_MMA (4 * STG)

__global__ void __launch_bounds__(256, 1)
mma_level_kernel(const __half* __restrict__ A_g,    // (rows,512) view
                 const float* __restrict__ c_prev,   // (rows,512) view
                 const int* __restrict__ node_ids,
                 __half* __restrict__ h_out,
                 float* __restrict__ c_out,
                 int lev) {
    extern __shared__ __align__(128) char dsm[];
    const uint32_t sbase = smem_u32(dsm);

    const int rbase = blockIdx.x * 128;
    const int jbase = blockIdx.y * 64;
    const int tid = threadIdx.x;
    const int wid = tid >> 5;
    const int wr = wid >> 2;       // m-half 0..1 (64 rows each)
    const int wc = wid & 3;        // j-slice 0..3 (16 j each)
    const int lid = tid & 31;

    float acc[4][5][2][4];
#pragma unroll
    for (int i = 0; i < 4; i++)
#pragma unroll
        for (int g = 0; g < 5; g++)
#pragma unroll
            for (int u = 0; u < 2; u++)
#pragma unroll
                for (int e = 0; e < 4; e++) acc[i][g][u][e] = 0.0f;

    const int rA = lid & 15;
    const int hA = lid >> 4;
    const int rB = (lid & 7) + ((lid >> 4) << 3);
    const int hB = (lid >> 3) & 1;
    const int rxA = rA & 7;
    const int rxB = rB & 7;

    auto load_chunk = [&](int kc, int st) {
        const uint32_t S = sbase + st * STG;
        const int k0 = kc * 64;
        // A: 128 rows x 8 segs(16B) = 1024 copies, 4/thread
#pragma unroll
        for (int i = 0; i < 4; i++) {
            int c = i * 256 + tid;
            int r = c >> 3;
            int sg = c & 7;
            const __half* src = A_g + (size_t)(rbase + r) * 512 + k0 + sg * 8;
            CP_ASYNC16(S + r * 128 + ((sg ^ (r & 7)) << 4), src);
        }
        // B: 320 rows x 8 segs = 2560 copies, 10/thread
#pragma unroll
        for (int i = 0; i < 10; i++) {
            int c = i * 256 + tid;
            int n = c >> 3;
            int sg = c & 7;
            int g = n >> 6;
            int jj = n & 63;
            const __half* src = g_Bh + (size_t)(g * 256 + jbase + jj) * 512 + k0 + sg * 8;
            CP_ASYNC16(S + OFF_B + n * 128 + ((sg ^ (n & 7)) << 4), src);
        }
    };

    load_chunk(0, 0); CP_COMMIT();
    load_chunk(1, 1); CP_COMMIT();

    for (int kc = 0; kc < 8; kc++) {
        __syncthreads();                       // all warps done with chunk kc-1
        if (kc + 2 < 8) load_chunk(kc + 2, (kc + 2) & 3);
        CP_COMMIT();
        CP_WAIT2();                            // chunk kc landed (this thread)
        __syncthreads();                       // publish all threads' chunk kc
        const uint32_t S = sbase + (kc & 3) * STG;

#pragma unroll
        for (int kk = 0; kk < 4; kk++) {
            uint32_t am[4][4], bm[5][4];
            const int segA = ((kk << 1) + hA) ^ rxA;
            const int segB = ((kk << 1) + hB) ^ rxB;
#pragma unroll
            for (int i = 0; i < 4; i++)
                LDSM4(am[i], S + (wr * 64 + i * 16 + rA) * 128 + (segA << 4));
#pragma unroll
            for (int g = 0; g < 5; g++)
                LDSM4(bm[g], S + OFF_B + (g * 64 + wc * 16 + rB) * 128 + (segB << 4));
#pragma unroll
            for (int i = 0; i < 4; i++)
#pragma unroll
                for (int g = 0; g < 5; g++) {
                    MMA16816(acc[i][g][0], am[i], bm[g][0], bm[g][1]);
                    MMA16816(acc[i][g][1], am[i], bm[g][2], bm[g][3]);
                }
        }
    }

    // ---- register epilogue: gate + direct stores ----
    const int n = 1 << lev;
    const int off = n - 2;
#pragma unroll
    for (int i = 0; i < 4; i++) {
#pragma unroll
        for (int mh = 0; mh < 2; mh++) {
            int m = wr * 64 + i * 16 + (lid >> 2) + mh * 8;
            int row = rbase + m;
            int bb = row >> lev;
            int jn = row & (n - 1);
            int id = node_ids[bb * TOTAL_NODES + off + jn];
            const float* gt = g_Gtab + id * 1024;
#pragma unroll
            for (int u = 0; u < 2; u++) {
                int j = wc * 16 + u * 8 + (lid & 3) * 2;
                int jg = jbase + j;
                float2 g0 = *(const float2*)(gt + jg);
                float2 g1 = *(const float2*)(gt + 256 + jg);
                float2 g2 = *(const float2*)(gt + 512 + jg);
                float2 g3 = *(const float2*)(gt + 768 + jg);
                float2 cl = *(const float2*)(c_prev + (size_t)row * 512 + jg);
                float2 cr = *(const float2*)(c_prev + (size_t)row * 512 + 256 + jg);
                float p0x = acc[i][0][u][mh * 2 + 0] + g0.x;
                float p0y = acc[i][0][u][mh * 2 + 1] + g0.y;
                float p1x = acc[i][1][u][mh * 2 + 0] + g0.x;
                float p1y = acc[i][1][u][mh * 2 + 1] + g0.y;
                float p2x = acc[i][2][u][mh * 2 + 0] + g1.x;
                float p2y = acc[i][2][u][mh * 2 + 1] + g1.y;
                float p3x = acc[i][3][u][mh * 2 + 0] + g2.x;
                float p3y = acc[i][3][u][mh * 2 + 1] + g2.y;
                float p4x = acc[i][4][u][mh * 2 + 0] + g3.x;
                float p4y = acc[i][4][u][mh * 2 + 1] + g3.y;
                float2 cc;
                cc.x = fsig(p2x) * ftanh(p4x) + fsig(p0x) * cl.x + fsig(p1x) * cr.x;
                cc.y = fsig(p2y) * ftanh(p4y) + fsig(p0y) * cl.y + fsig(p1y) * cr.y;
                float hx = fsig(p3x) * ftanh(cc.x);
                float hy = fsig(p3y) * ftanh(cc.y);
                size_t o = (size_t)row * 256 + jg;
                *(float2*)(c_out + o) = cc;
                *(__half2*)(h_out + o) = __floats2half2_rn(hx, hy);
                if (lev == 1) *(float2*)(g_hroot + o) = make_float2(hx, hy);
            }
        }
    }
}

// ---------------- final: scores + root_hidden ------------------------------
__global__ void final_kernel(const float* __restrict__ Wsm,
                             const float* __restrict__ bs,
                             float* __restrict__ out, int out_size) {
    int b = blockIdx.x;
    int t = threadIdx.x;
    __shared__ float hs[512];
    for (int jj = t; jj < 512; jj += 256) {
        float v = g_hroot[b * 512 + jj];
        hs[jj] = v;
        if (out_size >= 192 + 64 * 512) out[192 + b * 512 + jj] = v;
    }
    __syncthreads();
    if (t < 3) {
        float s = bs[t];
        for (int jj = 0; jj < 512; jj++) s += hs[jj] * Wsm[jj * 3 + t];
        out[b * 3 + t] = s;
    }
}

extern "C" void kernel_launch(void* const* d_in, const int* in_sizes, int n_in,
                              void* d_out, int out_size) {
    const int* node_ids = (const int*)d_in[0];
    const float* emb = (const float*)d_in[1];
    const float* W = (const float*)d_in[2];
    const float* bW = (const float*)d_in[3];
    const float* U = (const float*)d_in[4];
    const float* Ws = (const float*)d_in[5];
    const float* bs = (const float*)d_in[6];
    float* out = (float*)d_out;

    __half *h0, *h1;
    float *c0, *c1;
    cudaGetSymbolAddress((void**)&h0, g_h0);
    cudaGetSymbolAddress((void**)&c0, g_c0);
    cudaGetSymbolAddress((void**)&h1, g_h1);
    cudaGetSymbolAddress((void**)&c1, g_c1);

    cudaFuncSetAttribute(mma_level_kernel,
                         cudaFuncAttributeMaxDynamicSharedMemorySize, SMEM_MMA);

    prep1_kernel<<<64, 256>>>(emb, W, bW);
    prep2_kernel<<<dim3(64, 10), 256>>>(U);
    prep3_kernel<<<640, 1024>>>(U);

    level9_kernel<<<8192, 256>>>(node_ids, h0, c0);

    __half *hp = h0, *hc = h1;
    float *cp = c0, *cc = c1;
    for (int lev = 8; lev >= 1; lev--) {
        int rows = 64 << lev;
        dim3 grid(rows / 128, 4);
        mma_level_kernel<<<grid, 256, SMEM_MMA>>>(hp, cp, node_ids, hc, cc, lev);
        __half* t1 = hp; hp = hc; hc = t1;
        float* t2 = cp; cp = cc; cc = t2;
    }
    final_kernel<<<64, 256>>>(Ws, bs, out, out_size);
}

// round 13
// speedup vs baseline: 4.1527x; 1.1740x over previous
#include <cuda_runtime.h>
#include <cuda_fp16.h>
#include <cstdint>

// TreeLSTM B=64, L=10, H=E=256, V=64, TOTAL=2046.
//  - Gtab/Htab/Ctab tabulated per vocab id; level-9 U-GEMM tabulated (TL/TR)
//  - levels 8..1: mma.sync fp16 single-pass, register-only gating epilogue.
//    Template CM (128 big / 64 / 32 small levels) so every level fills ~148
//    CTAs in one wave; 4-stage cp.async ring.

#define TOTAL_NODES 2046

// ---------------- scratch ----------------
__device__ __half g_h0[32768 * 256];
__device__ float  g_c0[32768 * 256];
__device__ __half g_h1[16384 * 256];
__device__ float  g_c1[16384 * 256];
__device__ float  g_hroot[128 * 256];    // fp32 h at level 1
__device__ float g_Gtab[64 * 4 * 256];
__device__ float g_Htab[64 * 256];
__device__ float g_Ctab[64 * 256];
__device__ float g_TL[64 * 5 * 256];
__device__ float g_TR[64 * 5 * 256];
__device__ __half g_Bh[5 * 256 * 512];   // [g][n][k]  k = s*256+h, fp16 rounded

// ---------------- helpers ----------------
__device__ __forceinline__ float ftanh(float x) {
    float y; asm("tanh.approx.f32 %0, %1;" : "=f"(y) : "f"(x)); return y;
}
__device__ __forceinline__ float fsig(float x) { return 0.5f * ftanh(0.5f * x) + 0.5f; }

__device__ __forceinline__ uint32_t smem_u32(const void* p) {
    uint32_t a;
    asm("{ .reg .u64 t; cvta.to.shared.u64 t, %1; cvt.u32.u64 %0, t; }" : "=r"(a) : "l"(p));
    return a;
}

#define CP_ASYNC16(dst, src) \
    asm volatile("cp.async.cg.shared.global [%0], [%1], 16;" :: "r"(dst), "l"(src) : "memory")
#define CP_COMMIT() asm volatile("cp.async.commit_group;" ::: "memory")
#define CP_WAIT2()  asm volatile("cp.async.wait_group 2;" ::: "memory")

#define LDSM4(r, a) \
    asm volatile("ldmatrix.sync.aligned.m8n8.x4.shared.b16 {%0,%1,%2,%3}, [%4];" \
        : "=r"((r)[0]), "=r"((r)[1]), "=r"((r)[2]), "=r"((r)[3]) : "r"(a))

#define MMA16816(c, a, b0, b1) \
    asm volatile("mma.sync.aligned.m16n8k16.row.col.f32.f16.f16.f32 " \
        "{%0,%1,%2,%3}, {%4,%5,%6,%7}, {%8,%9}, {%0,%1,%2,%3};" \
        : "+f"((c)[0]), "+f"((c)[1]), "+f"((c)[2]), "+f"((c)[3]) \
        : "r"((a)[0]), "r"((a)[1]), "r"((a)[2]), "r"((a)[3]), "r"(b0), "r"(b1))

// ---------------- prep 1: Gtab, Htab, Ctab --------------------------------
__global__ void prep1_kernel(const float* __restrict__ emb,
                             const float* __restrict__ W,
                             const float* __restrict__ bW) {
    int v = blockIdx.x;
    int h = threadIdx.x;
    __shared__ float e[256];
    e[h] = emb[v * 256 + h];
    __syncthreads();
    float xg[4];
#pragma unroll
    for (int g = 0; g < 4; g++) {
        float s = bW[g * 256 + h];
        const float* Wg = W + g * 256 * 256 + h;
        for (int k = 0; k < 256; k++) s += e[k] * Wg[k * 256];
        xg[g] = s;
        g_Gtab[v * 1024 + g * 256 + h] = s;
    }
    float ig = fsig(xg[1]);
    float og = fsig(xg[2]);
    float ug = ftanh(xg[3]);
    float cc = ig * ug;
    g_Ctab[v * 256 + h] = cc;
    g_Htab[v * 256 + h] = og * ftanh(cc);
}

// ---------------- prep 2: TL/TR  (grid (64,10): v x (g,s)) -----------------
__global__ void prep2_kernel(const float* __restrict__ U) {
    int v = blockIdx.x;
    int g = blockIdx.y >> 1;
    int s = blockIdx.y & 1;
    int k = threadIdx.x;
    __shared__ float hh[256];
    hh[k] = g_Htab[v * 256 + k];
    __syncthreads();
    float* T = (s == 0) ? g_TL : g_TR;
    float acc = 0.0f;
    const float* Ug = U + ((g * 2 + s) * 256) * 256 + k;
    for (int h = 0; h < 256; h++) acc += hh[h] * Ug[h * 256];
    T[v * 1280 + g * 256 + k] = acc;
}

// ---------------- prep 3: B fp16 plane [g][n][k] ---------------------------
__global__ void prep3_kernel(const float* __restrict__ U) {
    int idx = blockIdx.x * blockDim.x + threadIdx.x;  // 5*256*512 = 655360
    if (idx >= 5 * 256 * 512) return;
    int k = idx & 511;
    int n = (idx >> 9) & 255;
    int g = idx >> 17;
    int s = k >> 8;
    int h = k & 255;
    g_Bh[idx] = __float2half_rn(U[((g * 2 + s) * 256 + h) * 256 + n]);
}

// ---------------- level 9: gather + gating (float4, 4 rows/block) ----------
__global__ void level9_kernel(const int* __restrict__ node_ids,
                              __half* __restrict__ hout,
                              float* __restrict__ cout) {
    int t = threadIdx.x;
    int row = blockIdx.x * 4 + (t >> 6);
    int jq = (t & 63);
    int bb = row >> 9;
    int jn = row & 511;
    const int* nr = node_ids + bb * TOTAL_NODES;
    int id  = nr[510 + jn];
    int idL = nr[1022 + 2 * jn];
    int idR = nr[1023 + 2 * jn];
    const float* tl = g_TL + idL * 1280 + jq * 4;
    const float* tr = g_TR + idR * 1280 + jq * 4;
    const float* gt = g_Gtab + id * 1024 + jq * 4;
    float4 t0l = *(const float4*)(tl);
    float4 t1l = *(const float4*)(tl + 256);
    float4 t2l = *(const float4*)(tl + 512);
    float4 t3l = *(const float4*)(tl + 768);
    float4 t4l = *(const float4*)(tl + 1024);
    float4 t0r = *(const float4*)(tr);
    float4 t1r = *(const float4*)(tr + 256);
    float4 t2r = *(const float4*)(tr + 512);
    float4 t3r = *(const float4*)(tr + 768);
    float4 t4r = *(const float4*)(tr + 1024);
    float4 gg0 = *(const float4*)(gt);
    float4 gg1 = *(const float4*)(gt + 256);
    float4 gg2 = *(const float4*)(gt + 512);
    float4 gg3 = *(const float4*)(gt + 768);
    float4 cl4 = *(const float4*)(g_Ctab + idL * 256 + jq * 4);
    float4 cr4 = *(const float4*)(g_Ctab + idR * 256 + jq * 4);
    float cv[4], hv[4];
#pragma unroll
    for (int e = 0; e < 4; e++) {
        float p0 = ((const float*)&t0l)[e] + ((const float*)&t0r)[e] + ((const float*)&gg0)[e];
        float p1 = ((const float*)&t1l)[e] + ((const float*)&t1r)[e] + ((const float*)&gg0)[e];
        float p2 = ((const float*)&t2l)[e] + ((const float*)&t2r)[e] + ((const float*)&gg1)[e];
        float p3 = ((const float*)&t3l)[e] + ((const float*)&t3r)[e] + ((const float*)&gg2)[e];
        float p4 = ((const float*)&t4l)[e] + ((const float*)&t4r)[e] + ((const float*)&gg3)[e];
        float cl = ((const float*)&cl4)[e];
        float cr = ((const float*)&cr4)[e];
        float cc = fsig(p2) * ftanh(p4) + fsig(p0) * cl + fsig(p1) * cr;
        cv[e] = cc;
        hv[e] = fsig(p3) * ftanh(cc);
    }
    size_t o = (size_t)row * 256 + jq * 4;
    *(float4*)(cout + o) = make_float4(cv[0], cv[1], cv[2], cv[3]);
    __half2 h01 = __floats2half2_rn(hv[0], hv[1]);
    __half2 h23 = __floats2half2_rn(hv[2], hv[3]);
    *(uint2*)(hout + o) = make_uint2(*(uint32_t*)&h01, *(uint32_t*)&h23);
}

// ---------------- mma.sync level kernel (levels 8..1) ----------------------
// CTA: CM rows x 64 j x 5 gates, K=512 in 8 chunks of 64. 256 threads.
// 8 warps: wr=wid>>2 m-half (CM/2 rows), wc=wid&3 j-slice (16 j). NI=CM/32.
// SMEM stage: A[CM][128B] B[320][128B], XOR seg-swizzle, 4-stage ring.
template <int CM>
__global__ void __launch_bounds__(256, 1)
mma_level_kernel(const __half* __restrict__ A_g,    // (rows,512) view
                 const float* __restrict__ c_prev,   // (rows,512) view
                 const int* __restrict__ node_ids,
                 __half* __restrict__ h_out,
                 float* __restrict__ c_out,
                 int lev) {
    constexpr int NI = CM / 32;             // m16-frags per warp
    constexpr int OFF_B = CM * 128;
    constexpr int STG = (CM + 320) * 128;
    constexpr int ACPT = CM / 32;           // A cp.async per thread

    extern __shared__ __align__(128) char dsm[];
    const uint32_t sbase = smem_u32(dsm);

    const int rbase = blockIdx.x * CM;
    const int jbase = blockIdx.y * 64;
    const int tid = threadIdx.x;
    const int wid = tid >> 5;
    const int wr = wid >> 2;       // m-half 0..1 (CM/2 rows each)
    const int wc = wid & 3;        // j-slice 0..3 (16 j each)
    const int lid = tid & 31;

    float acc[NI][5][2][4];
#pragma unroll
    for (int i = 0; i < NI; i++)
#pragma unroll
        for (int g = 0; g < 5; g++)
#pragma unroll
            for (int u = 0; u < 2; u++)
#pragma unroll
                for (int e = 0; e < 4; e++) acc[i][g][u][e] = 0.0f;

    const int rA = lid & 15;
    const int hA = lid >> 4;
    const int rB = (lid & 7) + ((lid >> 4) << 3);
    const int hB = (lid >> 3) & 1;
    const int rxA = rA & 7;
    const int rxB = rB & 7;

    auto load_chunk = [&](int kc, int st) {
        const uint32_t S = sbase + st * STG;
        const int k0 = kc * 64;
        // A: CM rows x 8 segs(16B) = CM*8 copies, ACPT/thread
#pragma unroll
        for (int i = 0; i < ACPT; i++) {
            int c = i * 256 + tid;
            int r = c >> 3;
            int sg = c & 7;
            const __half* src = A_g + (size_t)(rbase + r) * 512 + k0 + sg * 8;
            CP_ASYNC16(S + r * 128 + ((sg ^ (r & 7)) << 4), src);
        }
        // B: 320 rows x 8 segs = 2560 copies, 10/thread
#pragma unroll
        for (int i = 0; i < 10; i++) {
            int c = i * 256 + tid;
            int n = c >> 3;
            int sg = c & 7;
            int g = n >> 6;
            int jj = n & 63;
            const __half* src = g_Bh + (size_t)(g * 256 + jbase + jj) * 512 + k0 + sg * 8;
            CP_ASYNC16(S + OFF_B + n * 128 + ((sg ^ (n & 7)) << 4), src);
        }
    };

    load_chunk(0, 0); CP_COMMIT();
    load_chunk(1, 1); CP_COMMIT();

    for (int kc = 0; kc < 8; kc++) {
        __syncthreads();                       // all warps done with chunk kc-1
        if (kc + 2 < 8) load_chunk(kc + 2, (kc + 2) & 3);
        CP_COMMIT();
        CP_WAIT2();                            // chunk kc landed (this thread)
        __syncthreads();                       // publish all threads' chunk kc
        const uint32_t S = sbase + (kc & 3) * STG;

#pragma unroll
        for (int kk = 0; kk < 4; kk++) {
            uint32_t am[NI][4], bm[5][4];
            const int segA = ((kk << 1) + hA) ^ rxA;
            const int segB = ((kk << 1) + hB) ^ rxB;
#pragma unroll
            for (int i = 0; i < NI; i++)
                LDSM4(am[i], S + (wr * (CM / 2) + i * 16 + rA) * 128 + (segA << 4));
#pragma unroll
            for (int g = 0; g < 5; g++)
                LDSM4(bm[g], S + OFF_B + (g * 64 + wc * 16 + rB) * 128 + (segB << 4));
#pragma unroll
            for (int i = 0; i < NI; i++)
#pragma unroll
                for (int g = 0; g < 5; g++) {
                    MMA16816(acc[i][g][0], am[i], bm[g][0], bm[g][1]);
                    MMA16816(acc[i][g][1], am[i], bm[g][2], bm[g][3]);
                }
        }
    }

    // ---- register epilogue: gate + direct stores ----
    const int n = 1 << lev;
    const int off = n - 2;
#pragma unroll
    for (int i = 0; i < NI; i++) {
#pragma unroll
        for (int mh = 0; mh < 2; mh++) {
            int m = wr * (CM / 2) + i * 16 + (lid >> 2) + mh * 8;
            int row = rbase + m;
            int bb = row >> lev;
            int jn = row & (n - 1);
            int id = node_ids[bb * TOTAL_NODES + off + jn];
            const float* gt = g_Gtab + id * 1024;
#pragma unroll
            for (int u = 0; u < 2; u++) {
                int j = wc * 16 + u * 8 + (lid & 3) * 2;
                int jg = jbase + j;
                float2 g0 = *(const float2*)(gt + jg);
                float2 g1 = *(const float2*)(gt + 256 + jg);
                float2 g2 = *(const float2*)(gt + 512 + jg);
                float2 g3 = *(const float2*)(gt + 768 + jg);
                float2 cl = *(const float2*)(c_prev + (size_t)row * 512 + jg);
                float2 cr = *(const float2*)(c_prev + (size_t)row * 512 + 256 + jg);
                float p0x = acc[i][0][u][mh * 2 + 0] + g0.x;
                float p0y = acc[i][0][u][mh * 2 + 1] + g0.y;
                float p1x = acc[i][1][u][mh * 2 + 0] + g0.x;
                float p1y = acc[i][1][u][mh * 2 + 1] + g0.y;
                float p2x = acc[i][2][u][mh * 2 + 0] + g1.x;
                float p2y = acc[i][2][u][mh * 2 + 1] + g1.y;
                float p3x = acc[i][3][u][mh * 2 + 0] + g2.x;
                float p3y = acc[i][3][u][mh * 2 + 1] + g2.y;
                float p4x = acc[i][4][u][mh * 2 + 0] + g3.x;
                float p4y = acc[i][4][u][mh * 2 + 1] + g3.y;
                float2 cc;
                cc.x = fsig(p2x) * ftanh(p4x) + fsig(p0x) * cl.x + fsig(p1x) * cr.x;
                cc.y = fsig(p2y) * ftanh(p4y) + fsig(p0y) * cl.y + fsig(p1y) * cr.y;
                float hx = fsig(p3x) * ftanh(cc.x);
                float hy = fsig(p3y) * ftanh(cc.y);
                size_t o = (size_t)row * 256 + jg;
                *(float2*)(c_out + o) = cc;
                *(__half2*)(h_out + o) = __floats2half2_rn(hx, hy);
                if (lev == 1) *(float2*)(g_hroot + o) = make_float2(hx, hy);
            }
        }
    }
}

// ---------------- final: scores + root_hidden ------------------------------
__global__ void final_kernel(const float* __restrict__ Wsm,
                             const float* __restrict__ bs,
                             float* __restrict__ out, int out_size) {
    int b = blockIdx.x;
    int t = threadIdx.x;
    __shared__ float hs[512];
    for (int jj = t; jj < 512; jj += 256) {
        float v = g_hroot[b * 512 + jj];
        hs[jj] = v;
        if (out_size >= 192 + 64 * 512) out[192 + b * 512 + jj] = v;
    }
    __syncthreads();
    if (t < 3) {
        float s = bs[t];
        for (int jj = 0; jj < 512; jj++) s += hs[jj] * Wsm[jj * 3 + t];
        out[b * 3 + t] = s;
    }
}

extern "C" void kernel_launch(void* const* d_in, const int* in_sizes, int n_in,
                              void* d_out, int out_size) {
    const int* node_ids = (const int*)d_in[0];
    const float* emb = (const float*)d_in[1];
    const float* W = (const float*)d_in[2];
    const float* bW = (const float*)d_in[3];
    const float* U = (const float*)d_in[4];
    const float* Ws = (const float*)d_in[5];
    const float* bs = (const float*)d_in[6];
    float* out = (float*)d_out;

    __half *h0, *h1;
    float *c0, *c1;
    cudaGetSymbolAddress((void**)&h0, g_h0);
    cudaGetSymbolAddress((void**)&c0, g_c0);
    cudaGetSymbolAddress((void**)&h1, g_h1);
    cudaGetSymbolAddress((void**)&c1, g_c1);

    cudaFuncSetAttribute(mma_level_kernel<128>,
                         cudaFuncAttributeMaxDynamicSharedMemorySize, 4 * (128 + 320) * 128);
    cudaFuncSetAttribute(mma_level_kernel<64>,
                         cudaFuncAttributeMaxDynamicSharedMemorySize, 4 * (64 + 320) * 128);
    cudaFuncSetAttribute(mma_level_kernel<32>,
                         cudaFuncAttributeMaxDynamicSharedMemorySize, 4 * (32 + 320) * 128);

    prep1_kernel<<<64, 256>>>(emb, W, bW);
    prep2_kernel<<<dim3(64, 10), 256>>>(U);
    prep3_kernel<<<640, 1024>>>(U);

    level9_kernel<<<8192, 256>>>(node_ids, h0, c0);

    __half *hp = h0, *hc = h1;
    float *cp = c0, *cc = c1;
    for (int lev = 8; lev >= 1; lev--) {
        int rows = 64 << lev;
        if (lev >= 6) {
            dim3 grid(rows / 128, 4);
            mma_level_kernel<128><<<grid, 256, 4 * (128 + 320) * 128>>>(
                hp, cp, node_ids, hc, cc, lev);
        } else if (lev == 5) {
            dim3 grid(rows / 64, 4);
            mma_level_kernel<64><<<grid, 256, 4 * (64 + 320) * 128>>>(
                hp, cp, node_ids, hc, cc, lev);
        } else {
            dim3 grid(rows / 32, 4);
            mma_level_kernel<32><<<grid, 256, 4 * (32 + 320) * 128>>>(
                hp, cp, node_ids, hc, cc, lev);
        }
        __half* t1 = hp; hp = hc; hc = t1;
        float* t2 = cp; cp = cc; cc = t2;
    }
    final_kernel<<<64, 256>>>(Ws, bs, out, out_size);
}